// round 10
// baseline (speedup 1.0000x reference)
#include <cuda_runtime.h>
#include <math.h>

// Problem shapes (fixed)
#define S_LEN 256
#define BATCH 64
#define HSZ   1024
#define H3    3072
#define PLEN  256
#define PSZ   1024
// Output layout: [h_last (64*1024) | hs (256*64*2048) | attn (256*256*64)]
#define HS_OFF   65536
#define ATTN_OFF 33619968
#define NEGV -1000000000.0f

// Persistent recurrence config
#define GRID_P 128          // co-resident CTAs (<= 148 SMs, 3072/128 = 24)
#define ROWS_PER_CTA 24
#define JS_PER_CTA 8        // 1024/128
#define KCH 128             // k-chunk
#define NCH 8               // 1024/KCH

typedef unsigned long long ull;

// ---------------- device scratch (no runtime allocation allowed) -----------
__device__ float g_gi[(size_t)S_LEN * BATCH * H3];       // 201 MB
__device__ float g_q[(size_t)S_LEN * BATCH * PSZ];       //  64 MB
__device__ float g_scores[(size_t)BATCH * S_LEN * PLEN]; //  16 MB
__device__ float g_attnT[(size_t)BATCH * S_LEN * PLEN];  //  16 MB
__device__ float g_gh[(size_t)BATCH * H3];               // 786 KB
__device__ float g_hbuf[2][BATCH][HSZ];                  // 512 KB ping-pong
__device__ ull   g_bar;

// ---------------- packed fp32x2 helpers (Blackwell FFMA2 path) -------------
__device__ __forceinline__ ull pk2(float lo, float hi) {
    ull r;
    asm("mov.b64 %0, {%1, %2};" : "=l"(r) : "f"(lo), "f"(hi));
    return r;
}
__device__ __forceinline__ float2 upk2(ull v) {
    float2 r;
    asm("mov.b64 {%0, %1}, %2;" : "=f"(r.x), "=f"(r.y) : "l"(v));
    return r;
}
__device__ __forceinline__ void f2fma(ull &c, ull a, ull b) {
    asm("fma.rn.f32x2 %0, %1, %2, %0;" : "+l"(c) : "l"(a), "l"(b));
}

// ---------------- grid-wide barrier (monotonic counter, reset per launch) --
__device__ __forceinline__ void grid_bar() {
    __threadfence();          // release: all my prior global writes visible
    __syncthreads();          // all threads of CTA fenced before arrive
    if (threadIdx.x == 0) {
        ull t = atomicAdd(&g_bar, 1ULL) + 1ULL;
        ull target = ((t + GRID_P - 1) / GRID_P) * GRID_P;
        while (*((volatile ull*)&g_bar) < target) { }
    }
    __syncthreads();          // execution barrier: loads after this can't hoist
}

// ===========================================================================
// init: reset barrier counter, broadcast h_init into ping buffer 0
// ===========================================================================
__global__ void init_kernel(const float* __restrict__ h_init) {
    if (blockIdx.x == 0 && threadIdx.x == 0) g_bar = 0ULL;
    int b = blockIdx.x;  // 64 blocks
    ((float4*)&g_hbuf[0][b][0])[threadIdx.x] = ((const float4*)h_init)[threadIdx.x];
}

// ===========================================================================
// Persistent recurrence kernel. grid=128, 256 threads.
// Per step: phase A  gh[b][rows 24] = h @ W_hh^T   (k-packed FFMA2)
//           barrier
//           phase B  GRU gates for 8 hidden units x 64 b, write hs + h ping
//           barrier
// ===========================================================================
__global__ void __launch_bounds__(256) recurrence_kernel(
    const float* __restrict__ W, const float* __restrict__ gi,
    const float* __restrict__ bhh, const int* __restrict__ length,
    float* __restrict__ hs_out)
{
    __shared__ __align__(16) float Hs[64][KCH + 4];      // 33.8 KB (pad: pitch%128B==16)
    __shared__ __align__(16) float Ws[ROWS_PER_CTA][KCH];// 12.3 KB
    const int c = blockIdx.x, tid = threadIdx.x;
    // compute map: 4 row-groups x 64 batches
    const int b  = tid & 63;
    const int rg = tid >> 6;
    // gate map: 64 batches x 4 j-pairs
    const int gb = tid >> 2;
    const int gj = c * JS_PER_CTA + (tid & 3) * 2;
    // preload gate constants
    const float br0 = bhh[gj],          br1 = bhh[gj + 1];
    const float bz0 = bhh[HSZ + gj],    bz1 = bhh[HSZ + gj + 1];
    const float bn0 = bhh[2*HSZ + gj],  bn1 = bhh[2*HSZ + gj + 1];
    const int mylen = length[gb];
    const long long rowbase = (long long)c * ROWS_PER_CTA;

    int p = 0;
    for (int s = 0; s < S_LEN; s++) {
        const float* hcur = &g_hbuf[p][0][0];
        // -------- phase A: gh rows [rowbase, rowbase+24) --------
        ull a0 = 0, a1 = 0, a2 = 0, a3 = 0, a4 = 0, a5 = 0;
        float4 hre[8];
        float4 wre[3];
        // prefetch chunk 0 (fully coalesced: flat float4 index t + 256*i)
#pragma unroll
        for (int i = 0; i < 8; i++) {
            int f = tid + i * 256;
            hre[i] = __ldcg(((const float4*)(hcur + (f >> 5) * HSZ)) + (f & 31));
        }
#pragma unroll
        for (int i = 0; i < 3; i++) {
            int idx = tid + i * 256;
            wre[i] = *(((const float4*)(W + (rowbase + (idx >> 5)) * HSZ)) + (idx & 31));
        }
        for (int kc = 0; kc < NCH; kc++) {
            __syncthreads();
#pragma unroll
            for (int i = 0; i < 8; i++) {
                int f = tid + i * 256;
                *(float4*)&Hs[f >> 5][(f & 31) * 4] = hre[i];
            }
#pragma unroll
            for (int i = 0; i < 3; i++) {
                int idx = tid + i * 256;
                *(float4*)&Ws[idx >> 5][(idx & 31) * 4] = wre[i];
            }
            __syncthreads();
            if (kc + 1 < NCH) {
                const float* hnxt = hcur + (kc + 1) * KCH;
                const float* wnxt = W + (kc + 1) * KCH;
#pragma unroll
                for (int i = 0; i < 8; i++) {
                    int f = tid + i * 256;
                    hre[i] = __ldcg(((const float4*)(hnxt + (f >> 5) * HSZ)) + (f & 31));
                }
#pragma unroll
                for (int i = 0; i < 3; i++) {
                    int idx = tid + i * 256;
                    wre[i] = *(((const float4*)(wnxt + (rowbase + (idx >> 5)) * HSZ)) + (idx & 31));
                }
            }
#pragma unroll 8
            for (int kq = 0; kq < KCH / 4; kq++) {
                ulonglong2 h2 = *(const ulonglong2*)&Hs[b][kq * 4];
                ulonglong2 w;
                w = *(const ulonglong2*)&Ws[rg * 6 + 0][kq * 4];
                f2fma(a0, w.x, h2.x); f2fma(a0, w.y, h2.y);
                w = *(const ulonglong2*)&Ws[rg * 6 + 1][kq * 4];
                f2fma(a1, w.x, h2.x); f2fma(a1, w.y, h2.y);
                w = *(const ulonglong2*)&Ws[rg * 6 + 2][kq * 4];
                f2fma(a2, w.x, h2.x); f2fma(a2, w.y, h2.y);
                w = *(const ulonglong2*)&Ws[rg * 6 + 3][kq * 4];
                f2fma(a3, w.x, h2.x); f2fma(a3, w.y, h2.y);
                w = *(const ulonglong2*)&Ws[rg * 6 + 4][kq * 4];
                f2fma(a4, w.x, h2.x); f2fma(a4, w.y, h2.y);
                w = *(const ulonglong2*)&Ws[rg * 6 + 5][kq * 4];
                f2fma(a5, w.x, h2.x); f2fma(a5, w.y, h2.y);
            }
        }
        {   // reduce k-even/odd lanes, store 6 contiguous rows for batch b
            float2 f0 = upk2(a0), f1 = upk2(a1), f2v = upk2(a2);
            float2 f3 = upk2(a3), f4v = upk2(a4), f5 = upk2(a5);
            float* gp = &g_gh[0] + (long long)b * H3 + rowbase + rg * 6;
            *(float2*)(gp + 0) = make_float2(f0.x + f0.y, f1.x + f1.y);
            *(float2*)(gp + 2) = make_float2(f2v.x + f2v.y, f3.x + f3.y);
            *(float2*)(gp + 4) = make_float2(f4v.x + f4v.y, f5.x + f5.y);
        }
        grid_bar();

        // -------- phase B: GRU gates for (gb, gj..gj+1) --------
        {
            const float* gis = gi + ((long long)s * BATCH + gb) * H3;
            const float* ghb = &g_gh[0] + (long long)gb * H3;
            float2 ghr = __ldcg((const float2*)(ghb + gj));
            float2 ghz = __ldcg((const float2*)(ghb + HSZ + gj));
            float2 ghn = __ldcg((const float2*)(ghb + 2 * HSZ + gj));
            float2 gir = *(const float2*)(gis + gj);
            float2 giz = *(const float2*)(gis + HSZ + gj);
            float2 gin = *(const float2*)(gis + 2 * HSZ + gj);
            float2 hp2 = __ldcg((const float2*)&g_hbuf[p][gb][gj]);
            float keep = (s < mylen) ? 1.f : 0.f;

            float r0 = 1.f / (1.f + expf(-(gir.x + ghr.x + br0)));
            float r1 = 1.f / (1.f + expf(-(gir.y + ghr.y + br1)));
            float z0 = 1.f / (1.f + expf(-(giz.x + ghz.x + bz0)));
            float z1 = 1.f / (1.f + expf(-(giz.y + ghz.y + bz1)));
            float n0 = tanhf(gin.x + r0 * (ghn.x + bn0));
            float n1 = tanhf(gin.y + r1 * (ghn.y + bn1));
            float h0 = (n0 + z0 * (hp2.x - n0)) * keep;
            float h1 = (n1 + z1 * (hp2.y - n1)) * keep;

            *(float2*)&g_hbuf[p ^ 1][gb][gj] = make_float2(h0, h1);
            *(float2*)(hs_out + ((long long)s * BATCH + gb) * 2048 + gj) = make_float2(h0, h1);
        }
        grid_bar();
        p ^= 1;
    }
}

// ===========================================================================
// C[M,N] = A[M,K] * B[N,K]^T (+bias). A,B K-contiguous. 128x128 tile, BK=8,
// 256 threads, 8x8 per-thread microtile, fp32x2 accumulation.
// ===========================================================================
__global__ void __launch_bounds__(256, 2) gemm_nt_kernel(
    const float* __restrict__ A, const float* __restrict__ B,
    const float* __restrict__ bias, float* __restrict__ C,
    int K, long long lda, long long ldb, long long ldc,
    long long bsA, long long bsB, long long bsC)
{
    __shared__ __align__(16) float As[8][128];
    __shared__ __align__(16) float Bs[8][128];
    long long bz = blockIdx.z;
    A += bz * bsA; B += bz * bsB; C += bz * bsC;
    int m0 = blockIdx.x * 128, n0 = blockIdx.y * 128;
    int tid = threadIdx.x;
    int lr = tid >> 1, lk = (tid & 1) * 4;
    const float* aP = A + (long long)(m0 + lr) * lda + lk;
    const float* bP = B + (long long)(n0 + lr) * ldb + lk;
    int ty = tid >> 4, tx = tid & 15;

    ull acc[8][4];
#pragma unroll
    for (int i = 0; i < 8; i++)
#pragma unroll
        for (int j = 0; j < 4; j++) acc[i][j] = 0ull;

    for (int k0 = 0; k0 < K; k0 += 8) {
        float4 av = *(const float4*)aP;
        float4 bv = *(const float4*)bP;
        __syncthreads();
        As[lk + 0][lr] = av.x; As[lk + 1][lr] = av.y;
        As[lk + 2][lr] = av.z; As[lk + 3][lr] = av.w;
        Bs[lk + 0][lr] = bv.x; Bs[lk + 1][lr] = bv.y;
        Bs[lk + 2][lr] = bv.z; Bs[lk + 3][lr] = bv.w;
        __syncthreads();
#pragma unroll
        for (int k = 0; k < 8; k++) {
            float4 a0 = *(const float4*)&As[k][ty * 8];
            float4 a1 = *(const float4*)&As[k][ty * 8 + 4];
            ull b0 = *(const ull*)&Bs[k][tx * 8];
            ull b1 = *(const ull*)&Bs[k][tx * 8 + 2];
            ull b2 = *(const ull*)&Bs[k][tx * 8 + 4];
            ull b3 = *(const ull*)&Bs[k][tx * 8 + 6];
            float a[8] = {a0.x, a0.y, a0.z, a0.w, a1.x, a1.y, a1.z, a1.w};
#pragma unroll
            for (int i = 0; i < 8; i++) {
                ull a2 = pk2(a[i], a[i]);
                f2fma(acc[i][0], a2, b0);
                f2fma(acc[i][1], a2, b1);
                f2fma(acc[i][2], a2, b2);
                f2fma(acc[i][3], a2, b3);
            }
        }
        aP += 8; bP += 8;
    }

    float bb[8];
#pragma unroll
    for (int j = 0; j < 8; j++) bb[j] = bias ? bias[n0 + tx * 8 + j] : 0.f;
#pragma unroll
    for (int i = 0; i < 8; i++) {
        float2 p0 = upk2(acc[i][0]), p1 = upk2(acc[i][1]);
        float2 p2 = upk2(acc[i][2]), p3 = upk2(acc[i][3]);
        float4 v0 = make_float4(p0.x + bb[0], p0.y + bb[1], p1.x + bb[2], p1.y + bb[3]);
        float4 v1 = make_float4(p2.x + bb[4], p2.y + bb[5], p3.x + bb[6], p3.y + bb[7]);
        float* cp = C + (long long)(m0 + ty * 8 + i) * ldc + n0 + tx * 8;
        *(float4*)cp = v0;
        *(float4*)(cp + 4) = v1;
    }
}

// ===========================================================================
// C[M,N] = A[M,K] * B[K,N]  (A K-contig rows, B N-contig rows).
// ===========================================================================
__global__ void __launch_bounds__(256, 2) gemm_nn_kernel(
    const float* __restrict__ A, const float* __restrict__ B,
    float* __restrict__ C,
    int K, long long lda, long long ldb, long long ldc,
    long long bsA, long long bsB, long long bsC)
{
    __shared__ __align__(16) float As[8][128];
    __shared__ __align__(16) float Bs[8][128];
    long long bz = blockIdx.z;
    A += bz * bsA; B += bz * bsB; C += bz * bsC;
    int m0 = blockIdx.x * 128, n0 = blockIdx.y * 128;
    int tid = threadIdx.x;
    int lr = tid >> 1, lk = (tid & 1) * 4;
    const float* aP = A + (long long)(m0 + lr) * lda + lk;
    int bRow = tid >> 5, bCol = (tid & 31) * 4;
    const float* bP = B + (long long)bRow * ldb + n0 + bCol;
    int ty = tid >> 4, tx = tid & 15;

    ull acc[8][4];
#pragma unroll
    for (int i = 0; i < 8; i++)
#pragma unroll
        for (int j = 0; j < 4; j++) acc[i][j] = 0ull;

    for (int k0 = 0; k0 < K; k0 += 8) {
        float4 av = *(const float4*)aP;
        float4 bv = *(const float4*)bP;
        __syncthreads();
        As[lk + 0][lr] = av.x; As[lk + 1][lr] = av.y;
        As[lk + 2][lr] = av.z; As[lk + 3][lr] = av.w;
        *(float4*)&Bs[bRow][bCol] = bv;
        __syncthreads();
#pragma unroll
        for (int k = 0; k < 8; k++) {
            float4 a0 = *(const float4*)&As[k][ty * 8];
            float4 a1 = *(const float4*)&As[k][ty * 8 + 4];
            ull b0 = *(const ull*)&Bs[k][tx * 8];
            ull b1 = *(const ull*)&Bs[k][tx * 8 + 2];
            ull b2 = *(const ull*)&Bs[k][tx * 8 + 4];
            ull b3 = *(const ull*)&Bs[k][tx * 8 + 6];
            float a[8] = {a0.x, a0.y, a0.z, a0.w, a1.x, a1.y, a1.z, a1.w};
#pragma unroll
            for (int i = 0; i < 8; i++) {
                ull a2 = pk2(a[i], a[i]);
                f2fma(acc[i][0], a2, b0);
                f2fma(acc[i][1], a2, b1);
                f2fma(acc[i][2], a2, b2);
                f2fma(acc[i][3], a2, b3);
            }
        }
        aP += 8; bP += 8 * ldb;
    }

#pragma unroll
    for (int i = 0; i < 8; i++) {
        float2 p0 = upk2(acc[i][0]), p1 = upk2(acc[i][1]);
        float2 p2 = upk2(acc[i][2]), p3 = upk2(acc[i][3]);
        float* cp = C + (long long)(m0 + ty * 8 + i) * ldc + n0 + tx * 8;
        *(float4*)cp = make_float4(p0.x, p0.y, p1.x, p1.y);
        *(float4*)(cp + 4) = make_float4(p2.x, p2.y, p3.x, p3.y);
    }
}

// ===========================================================================
// Masked softmax over l (PLEN) per (s, b). Writes attnT[b][s][l] and attn out.
// ===========================================================================
__global__ void __launch_bounds__(256) softmax_kernel(
    const float* __restrict__ scores, const int* __restrict__ post_length,
    float* __restrict__ attnT, float* __restrict__ attn_out)
{
    __shared__ float sm[256];
    int s = blockIdx.x, b = blockIdx.y, l = threadIdx.x;
    float sc = scores[((long long)b * S_LEN + s) * PLEN + l];
    if (l >= post_length[b]) sc = NEGV;
    sm[l] = sc; __syncthreads();
    for (int o = 128; o > 0; o >>= 1) {
        if (l < o) sm[l] = fmaxf(sm[l], sm[l + o]);
        __syncthreads();
    }
    float mx = sm[0]; __syncthreads();
    float e = expf(sc - mx);
    sm[l] = e; __syncthreads();
    for (int o = 128; o > 0; o >>= 1) {
        if (l < o) sm[l] += sm[l + o];
        __syncthreads();
    }
    float a = e / sm[0];
    attnT[((long long)b * S_LEN + s) * PLEN + l] = a;
    attn_out[(long long)s * (PLEN * BATCH) + (long long)l * BATCH + b] = a;
}

// h_last = hs[255][:, :1024]
__global__ void hlast_kernel(const float* __restrict__ src, float* __restrict__ dst)
{
    int b = blockIdx.x, t = threadIdx.x;
    float4 v = *(const float4*)(src + (long long)b * 2048 + t * 4);
    *(float4*)(dst + (long long)b * 1024 + t * 4) = v;
}

// ===========================================================================
extern "C" void kernel_launch(void* const* d_in, const int* in_sizes, int n_in,
                              void* d_out, int out_size)
{
    const float* incoming = (const float*)d_in[0];   // [256,64,1024]
    const float* post     = (const float*)d_in[1];   // [256,64,1024]
    const float* h_init   = (const float*)d_in[2];   // [1,1,1024]
    const float* W_ih     = (const float*)d_in[3];   // [3072,1024]
    const float* W_hh     = (const float*)d_in[4];   // [3072,1024]
    const float* b_ih     = (const float*)d_in[5];   // [3072]
    const float* b_hh     = (const float*)d_in[6];   // [3072]
    const float* Wq       = (const float*)d_in[7];   // [1024,1024]
    const float* bq       = (const float*)d_in[8];   // [1024]
    const int*   length   = (const int*)d_in[9];     // [64]
    const int*   plen     = (const int*)d_in[10];    // [64]
    float* out = (float*)d_out;

    float *gi, *q, *scores, *attnT;
    cudaGetSymbolAddress((void**)&gi,     g_gi);
    cudaGetSymbolAddress((void**)&q,      g_q);
    cudaGetSymbolAddress((void**)&scores, g_scores);
    cudaGetSymbolAddress((void**)&attnT,  g_attnT);

    // 1) gi = incoming @ W_ih^T + b_ih : [16384, 3072], K=1024
    gemm_nt_kernel<<<dim3(128, 24, 1), 256>>>(
        incoming, W_ih, b_ih, gi, 1024, 1024, 1024, 3072, 0, 0, 0);

    // 2) recurrence: one persistent kernel (barrier reset + init h)
    init_kernel<<<64, 256>>>(h_init);
    recurrence_kernel<<<GRID_P, 256>>>(W_hh, gi, b_hh, length, out + HS_OFF);

    // 3) queries = hs_h @ Wq^T + bq : [16384, 1024], A stride 2048
    gemm_nt_kernel<<<dim3(128, 8, 1), 256>>>(
        out + HS_OFF, Wq, bq, q, 1024, 2048, 1024, 1024, 0, 0, 0);

    // 4) scores[b][s][l] = q[s,b,:] . post[l,b,:]  (batched over b)
    gemm_nt_kernel<<<dim3(2, 2, 64), 256>>>(
        q, post, (const float*)0, scores, 1024,
        (long long)BATCH * PSZ, (long long)BATCH * PSZ, PLEN,
        PSZ, PSZ, (long long)S_LEN * PLEN);

    // 5) masked softmax over l; writes attnT and the attn output block
    softmax_kernel<<<dim3(256, 64), 256>>>(scores, plen, attnT, out + ATTN_OFF);

    // 6) context[s][b][p] = attnT[b][s][:] @ post[:,b,:]  (batched over b)
    gemm_nn_kernel<<<dim3(2, 8, 64), 256>>>(
        attnT, post, out + HS_OFF + 1024, PLEN,
        PLEN, (long long)BATCH * PSZ, (long long)BATCH * 2048,
        (long long)S_LEN * PLEN, PSZ, 2048);

    // 7) h_last = hs[255, :, :1024]
    hlast_kernel<<<64, 256>>>(out + HS_OFF + (long long)255 * BATCH * 2048, out);
}

// round 12
// speedup vs baseline: 1.5713x; 1.5713x over previous
#include <cuda_runtime.h>
#include <math.h>
#include <stdint.h>

// Problem shapes (fixed)
#define S_LEN 256
#define BATCH 64
#define HSZ   1024
#define H3    3072
#define PLEN  256
#define PSZ   1024
// Output layout: [h_last (64*1024) | hs (256*64*2048) | attn (256*256*64)]
#define HS_OFF   65536
#define ATTN_OFF 33619968
#define NEGV -1000000000.0f

// Persistent recurrence config
#define GRID_P 128          // 128 CTAs, each owns 8 hidden units (all 3 gates)
// dynamic smem layout (bytes)
#define SM_W    0           // Wsm[24][1024] floats = 98304
#define SM_HS   98304       // Hs[2][4][64][36] floats = 73728
#define SM_RED  172032      // red[4][24][66] floats = 25344
#define SM_TOTAL 197376
#define HSBUF   36864       // one Hs buffer (4*64*36*4)

typedef unsigned long long ull;

// ---------------- device scratch (no runtime allocation allowed) -----------
__device__ float g_gi[(size_t)S_LEN * BATCH * H3];       // 201 MB
__device__ float g_q[(size_t)S_LEN * BATCH * PSZ];       //  64 MB
__device__ float g_scores[(size_t)BATCH * S_LEN * PLEN]; //  16 MB
__device__ float g_attnT[(size_t)BATCH * S_LEN * PLEN];  //  16 MB
__device__ float g_hbuf[2][BATCH][HSZ];                  // 512 KB ping-pong
__device__ ull   g_bar;

// ---------------- packed fp32x2 helpers (Blackwell FFMA2 path) -------------
__device__ __forceinline__ ull pk2(float lo, float hi) {
    ull r;
    asm("mov.b64 %0, {%1, %2};" : "=l"(r) : "f"(lo), "f"(hi));
    return r;
}
__device__ __forceinline__ float2 upk2(ull v) {
    float2 r;
    asm("mov.b64 {%0, %1}, %2;" : "=f"(r.x), "=f"(r.y) : "l"(v));
    return r;
}
__device__ __forceinline__ void f2fma(ull &c, ull a, ull b) {
    asm("fma.rn.f32x2 %0, %1, %2, %0;" : "+l"(c) : "l"(a), "l"(b));
}

// ---------------- cp.async helpers ----------------------------------------
__device__ __forceinline__ void cp16(uint32_t dst, const void* src) {
    asm volatile("cp.async.cg.shared.global [%0], [%1], 16;\n"
                 :: "r"(dst), "l"(src) : "memory");
}
#define CP_COMMIT() asm volatile("cp.async.commit_group;\n" ::: "memory")
#define CP_WAIT1()  asm volatile("cp.async.wait_group 1;\n" ::: "memory")

// ---------------- grid-wide barrier ----------------------------------------
__device__ __forceinline__ void grid_bar() {
    __threadfence();          // release my writes
    __syncthreads();
    if (threadIdx.x == 0) {
        ull t = atomicAdd(&g_bar, 1ULL) + 1ULL;
        ull target = ((t + GRID_P - 1) / GRID_P) * GRID_P;
        while (*((volatile ull*)&g_bar) < target) { }
        __threadfence();      // acquire
    }
    __syncthreads();
}

// ===========================================================================
// init: reset barrier counter, broadcast h_init into ping buffer 0
// ===========================================================================
__global__ void init_kernel(const float* __restrict__ h_init) {
    if (blockIdx.x == 0 && threadIdx.x == 0) g_bar = 0ULL;
    int b = blockIdx.x;  // 64 blocks
    ((float4*)&g_hbuf[0][b][0])[threadIdx.x] = ((const float4*)h_init)[threadIdx.x];
}

// ===========================================================================
// Persistent recurrence kernel v2.  grid=128, 256 threads, ~193 KB dyn smem.
// CTA c owns hidden units j = c*8..c*8+7 -> W rows {j, 1024+j, 2048+j} (24).
// Per step: phase A (gh for 24 rows x 64 b, W in smem, h cp.async-staged),
// smem reduce over 4 k-slices, phase B gates (CTA-local), ONE grid barrier.
// ===========================================================================
__global__ void __launch_bounds__(256) recurrence2_kernel(
    const float* __restrict__ W, const float* __restrict__ gi,
    const float* __restrict__ bhh, const int* __restrict__ length,
    float* __restrict__ hs_out)
{
    extern __shared__ __align__(16) char smem[];
    float* Wsm = (float*)(smem + SM_W);     // [24][1024]
    float* red = (float*)(smem + SM_RED);   // [4][24][66]
    uint32_t sb;
    asm("{ .reg .u64 t; cvta.to.shared.u64 t, %1; cvt.u32.u64 %0, t; }"
        : "=r"(sb) : "l"(smem));
    const uint32_t hs_u32 = sb + SM_HS;

    const int c = blockIdx.x, tid = threadIdx.x;
    const int w = tid >> 5, lane = tid & 31;
    const int ks = w >> 1, rg = w & 1;      // k-slice 0..3, row-half 0..1
    const int b0 = lane, b1 = lane + 32;

    // ---- load W rows (gathered {r,z,n} x 8 units) once, coalesced ----
    for (int idx = tid; idx < 24 * 256; idx += 256) {
        int u = idx >> 8, f4 = idx & 255;
        long long grow = (long long)(u >> 3) * 1024 + c * 8 + (u & 7);
        *(float4*)&Wsm[u * 1024 + f4 * 4] =
            *(const float4*)&W[grow * 1024 + f4 * 4];
    }

    // ---- gate-phase constants (j fixed per thread; two batches) ----
    const int j  = tid & 7;
    const int bA = tid >> 3;        // 0..31
    const int bB = bA + 32;
    const float br = bhh[c * 8 + j];
    const float bz = bhh[HSZ + c * 8 + j];
    const float bn = bhh[2 * HSZ + c * 8 + j];
    const int lenA = length[bA], lenB = length[bB];

    __syncthreads();

    int p = 0;
    for (int s = 0; s < S_LEN; s++) {
        const float* hsrc = &g_hbuf[p][0][0];

        // prologue: stage chunks 0,1
#pragma unroll
        for (int cj = 0; cj < 2; cj++) {
#pragma unroll
            for (int i = 0; i < 8; i++) {
                int idx = tid + i * 256;
                int b = idx >> 5, kss = (idx >> 3) & 3, f4 = idx & 7;
                cp16(hs_u32 + cj * HSBUF + kss * 9216 + b * 144 + f4 * 16,
                     hsrc + (long long)b * 1024 + kss * 256 + cj * 32 + f4 * 4);
            }
            CP_COMMIT();
        }

        ull acc[12][2];
#pragma unroll
        for (int r = 0; r < 12; r++) { acc[r][0] = 0ull; acc[r][1] = 0ull; }

        for (int cj = 0; cj < 8; cj++) {
            CP_WAIT1();
            __syncthreads();
            const char* hb = smem + SM_HS + (cj & 1) * HSBUF + ks * 9216;
#pragma unroll
            for (int half = 0; half < 2; half++) {
                const int kk0 = half * 16;
                ull hA[8], hB[8];
                const ull* hpA = (const ull*)(hb + b0 * 144 + kk0 * 4);
                const ull* hpB = (const ull*)(hb + b1 * 144 + kk0 * 4);
#pragma unroll
                for (int i = 0; i < 8; i++) { hA[i] = hpA[i]; hB[i] = hpB[i]; }
#pragma unroll
                for (int r = 0; r < 12; r++) {
                    const ull* wp = (const ull*)&Wsm[(rg * 12 + r) * 1024 +
                                                     ks * 256 + cj * 32 + kk0];
#pragma unroll
                    for (int i = 0; i < 8; i++) {
                        ull wv = wp[i];
                        f2fma(acc[r][0], wv, hA[i]);
                        f2fma(acc[r][1], wv, hB[i]);
                    }
                }
            }
            __syncthreads();
            if (cj + 2 < 8) {
#pragma unroll
                for (int i = 0; i < 8; i++) {
                    int idx = tid + i * 256;
                    int b = idx >> 5, kss = (idx >> 3) & 3, f4 = idx & 7;
                    cp16(hs_u32 + (cj & 1) * HSBUF + kss * 9216 + b * 144 + f4 * 16,
                         hsrc + (long long)b * 1024 + kss * 256 + (cj + 2) * 32 + f4 * 4);
                }
            }
            CP_COMMIT();
        }

        // ---- reduce: write per-slice partials (pair-summed) ----
#pragma unroll
        for (int r = 0; r < 12; r++) {
            float2 e0 = upk2(acc[r][0]);
            float2 e1 = upk2(acc[r][1]);
            red[(ks * 24 + rg * 12 + r) * 66 + b0] = e0.x + e0.y;
            red[(ks * 24 + rg * 12 + r) * 66 + b1] = e1.x + e1.y;
        }
        __syncthreads();

        // ---- phase B: gates for (j, bA) and (j, bB), CTA-local ----
        {
            float srA = 0, szA = 0, snA = 0, srB = 0, szB = 0, snB = 0;
#pragma unroll
            for (int k4 = 0; k4 < 4; k4++) {
                srA += red[(k4 * 24 + j) * 66 + bA];
                srB += red[(k4 * 24 + j) * 66 + bB];
                szA += red[(k4 * 24 + 8 + j) * 66 + bA];
                szB += red[(k4 * 24 + 8 + j) * 66 + bB];
                snA += red[(k4 * 24 + 16 + j) * 66 + bA];
                snB += red[(k4 * 24 + 16 + j) * 66 + bB];
            }
            const float* giA = gi + ((long long)s * BATCH + bA) * H3 + c * 8 + j;
            const float* giB = gi + ((long long)s * BATCH + bB) * H3 + c * 8 + j;
            float girA = giA[0], gizA = giA[HSZ], ginA = giA[2 * HSZ];
            float girB = giB[0], gizB = giB[HSZ], ginB = giB[2 * HSZ];
            float hpA = g_hbuf[p][bA][c * 8 + j];
            float hpB = g_hbuf[p][bB][c * 8 + j];

            float rA = 1.f / (1.f + expf(-(girA + srA + br)));
            float zA = 1.f / (1.f + expf(-(gizA + szA + bz)));
            float nA = tanhf(ginA + rA * (snA + bn));
            float kA = (s < lenA) ? 1.f : 0.f;
            float hA2 = (nA + zA * (hpA - nA)) * kA;

            float rB = 1.f / (1.f + expf(-(girB + srB + br)));
            float zB = 1.f / (1.f + expf(-(gizB + szB + bz)));
            float nB = tanhf(ginB + rB * (snB + bn));
            float kB = (s < lenB) ? 1.f : 0.f;
            float hB2 = (nB + zB * (hpB - nB)) * kB;

            g_hbuf[p ^ 1][bA][c * 8 + j] = hA2;
            g_hbuf[p ^ 1][bB][c * 8 + j] = hB2;
            hs_out[((long long)s * BATCH + bA) * 2048 + c * 8 + j] = hA2;
            hs_out[((long long)s * BATCH + bB) * 2048 + c * 8 + j] = hB2;
        }
        grid_bar();
        p ^= 1;
    }
}

// ===========================================================================
// C[M,N] = A[M,K] * B[N,K]^T (+bias). A,B K-contiguous. 128x128 tile, BK=8,
// 256 threads, 8x8 per-thread microtile, fp32x2 accumulation.
// ===========================================================================
__global__ void __launch_bounds__(256, 2) gemm_nt_kernel(
    const float* __restrict__ A, const float* __restrict__ B,
    const float* __restrict__ bias, float* __restrict__ C,
    int K, long long lda, long long ldb, long long ldc,
    long long bsA, long long bsB, long long bsC)
{
    __shared__ __align__(16) float As[8][128];
    __shared__ __align__(16) float Bs[8][128];
    long long bz = blockIdx.z;
    A += bz * bsA; B += bz * bsB; C += bz * bsC;
    int m0 = blockIdx.x * 128, n0 = blockIdx.y * 128;
    int tid = threadIdx.x;
    int lr = tid >> 1, lk = (tid & 1) * 4;
    const float* aP = A + (long long)(m0 + lr) * lda + lk;
    const float* bP = B + (long long)(n0 + lr) * ldb + lk;
    int ty = tid >> 4, tx = tid & 15;

    ull acc[8][4];
#pragma unroll
    for (int i = 0; i < 8; i++)
#pragma unroll
        for (int j = 0; j < 4; j++) acc[i][j] = 0ull;

    for (int k0 = 0; k0 < K; k0 += 8) {
        float4 av = *(const float4*)aP;
        float4 bv = *(const float4*)bP;
        __syncthreads();
        As[lk + 0][lr] = av.x; As[lk + 1][lr] = av.y;
        As[lk + 2][lr] = av.z; As[lk + 3][lr] = av.w;
        Bs[lk + 0][lr] = bv.x; Bs[lk + 1][lr] = bv.y;
        Bs[lk + 2][lr] = bv.z; Bs[lk + 3][lr] = bv.w;
        __syncthreads();
#pragma unroll
        for (int k = 0; k < 8; k++) {
            float4 a0 = *(const float4*)&As[k][ty * 8];
            float4 a1 = *(const float4*)&As[k][ty * 8 + 4];
            ull b0 = *(const ull*)&Bs[k][tx * 8];
            ull b1 = *(const ull*)&Bs[k][tx * 8 + 2];
            ull b2 = *(const ull*)&Bs[k][tx * 8 + 4];
            ull b3 = *(const ull*)&Bs[k][tx * 8 + 6];
            float a[8] = {a0.x, a0.y, a0.z, a0.w, a1.x, a1.y, a1.z, a1.w};
#pragma unroll
            for (int i = 0; i < 8; i++) {
                ull a2 = pk2(a[i], a[i]);
                f2fma(acc[i][0], a2, b0);
                f2fma(acc[i][1], a2, b1);
                f2fma(acc[i][2], a2, b2);
                f2fma(acc[i][3], a2, b3);
            }
        }
        aP += 8; bP += 8;
    }

    float bb[8];
#pragma unroll
    for (int jj = 0; jj < 8; jj++) bb[jj] = bias ? bias[n0 + tx * 8 + jj] : 0.f;
#pragma unroll
    for (int i = 0; i < 8; i++) {
        float2 p0 = upk2(acc[i][0]), p1 = upk2(acc[i][1]);
        float2 p2 = upk2(acc[i][2]), p3 = upk2(acc[i][3]);
        float4 v0 = make_float4(p0.x + bb[0], p0.y + bb[1], p1.x + bb[2], p1.y + bb[3]);
        float4 v1 = make_float4(p2.x + bb[4], p2.y + bb[5], p3.x + bb[6], p3.y + bb[7]);
        float* cp = C + (long long)(m0 + ty * 8 + i) * ldc + n0 + tx * 8;
        *(float4*)cp = v0;
        *(float4*)(cp + 4) = v1;
    }
}

// ===========================================================================
// C[M,N] = A[M,K] * B[K,N]  (A K-contig rows, B N-contig rows).
// ===========================================================================
__global__ void __launch_bounds__(256, 2) gemm_nn_kernel(
    const float* __restrict__ A, const float* __restrict__ B,
    float* __restrict__ C,
    int K, long long lda, long long ldb, long long ldc,
    long long bsA, long long bsB, long long bsC)
{
    __shared__ __align__(16) float As[8][128];
    __shared__ __align__(16) float Bs[8][128];
    long long bz = blockIdx.z;
    A += bz * bsA; B += bz * bsB; C += bz * bsC;
    int m0 = blockIdx.x * 128, n0 = blockIdx.y * 128;
    int tid = threadIdx.x;
    int lr = tid >> 1, lk = (tid & 1) * 4;
    const float* aP = A + (long long)(m0 + lr) * lda + lk;
    int bRow = tid >> 5, bCol = (tid & 31) * 4;
    const float* bP = B + (long long)bRow * ldb + n0 + bCol;
    int ty = tid >> 4, tx = tid & 15;

    ull acc[8][4];
#pragma unroll
    for (int i = 0; i < 8; i++)
#pragma unroll
        for (int j = 0; j < 4; j++) acc[i][j] = 0ull;

    for (int k0 = 0; k0 < K; k0 += 8) {
        float4 av = *(const float4*)aP;
        float4 bv = *(const float4*)bP;
        __syncthreads();
        As[lk + 0][lr] = av.x; As[lk + 1][lr] = av.y;
        As[lk + 2][lr] = av.z; As[lk + 3][lr] = av.w;
        *(float4*)&Bs[bRow][bCol] = bv;
        __syncthreads();
#pragma unroll
        for (int k = 0; k < 8; k++) {
            float4 a0 = *(const float4*)&As[k][ty * 8];
            float4 a1 = *(const float4*)&As[k][ty * 8 + 4];
            ull b0 = *(const ull*)&Bs[k][tx * 8];
            ull b1 = *(const ull*)&Bs[k][tx * 8 + 2];
            ull b2 = *(const ull*)&Bs[k][tx * 8 + 4];
            ull b3 = *(const ull*)&Bs[k][tx * 8 + 6];
            float a[8] = {a0.x, a0.y, a0.z, a0.w, a1.x, a1.y, a1.z, a1.w};
#pragma unroll
            for (int i = 0; i < 8; i++) {
                ull a2 = pk2(a[i], a[i]);
                f2fma(acc[i][0], a2, b0);
                f2fma(acc[i][1], a2, b1);
                f2fma(acc[i][2], a2, b2);
                f2fma(acc[i][3], a2, b3);
            }
        }
        aP += 8; bP += 8 * ldb;
    }

#pragma unroll
    for (int i = 0; i < 8; i++) {
        float2 p0 = upk2(acc[i][0]), p1 = upk2(acc[i][1]);
        float2 p2 = upk2(acc[i][2]), p3 = upk2(acc[i][3]);
        float* cp = C + (long long)(m0 + ty * 8 + i) * ldc + n0 + tx * 8;
        *(float4*)cp = make_float4(p0.x, p0.y, p1.x, p1.y);
        *(float4*)(cp + 4) = make_float4(p2.x, p2.y, p3.x, p3.y);
    }
}

// ===========================================================================
// Masked softmax over l (PLEN) per (s, b). Writes attnT[b][s][l] and attn out.
// ===========================================================================
__global__ void __launch_bounds__(256) softmax_kernel(
    const float* __restrict__ scores, const int* __restrict__ post_length,
    float* __restrict__ attnT, float* __restrict__ attn_out)
{
    __shared__ float sm[256];
    int s = blockIdx.x, b = blockIdx.y, l = threadIdx.x;
    float sc = scores[((long long)b * S_LEN + s) * PLEN + l];
    if (l >= post_length[b]) sc = NEGV;
    sm[l] = sc; __syncthreads();
    for (int o = 128; o > 0; o >>= 1) {
        if (l < o) sm[l] = fmaxf(sm[l], sm[l + o]);
        __syncthreads();
    }
    float mx = sm[0]; __syncthreads();
    float e = expf(sc - mx);
    sm[l] = e; __syncthreads();
    for (int o = 128; o > 0; o >>= 1) {
        if (l < o) sm[l] += sm[l + o];
        __syncthreads();
    }
    float a = e / sm[0];
    attnT[((long long)b * S_LEN + s) * PLEN + l] = a;
    attn_out[(long long)s * (PLEN * BATCH) + (long long)l * BATCH + b] = a;
}

// h_last = hs[255][:, :1024]
__global__ void hlast_kernel(const float* __restrict__ src, float* __restrict__ dst)
{
    int b = blockIdx.x, t = threadIdx.x;
    float4 v = *(const float4*)(src + (long long)b * 2048 + t * 4);
    *(float4*)(dst + (long long)b * 1024 + t * 4) = v;
}

// ===========================================================================
extern "C" void kernel_launch(void* const* d_in, const int* in_sizes, int n_in,
                              void* d_out, int out_size)
{
    const float* incoming = (const float*)d_in[0];   // [256,64,1024]
    const float* post     = (const float*)d_in[1];   // [256,64,1024]
    const float* h_init   = (const float*)d_in[2];   // [1,1,1024]
    const float* W_ih     = (const float*)d_in[3];   // [3072,1024]
    const float* W_hh     = (const float*)d_in[4];   // [3072,1024]
    const float* b_ih     = (const float*)d_in[5];   // [3072]
    const float* b_hh     = (const float*)d_in[6];   // [3072]
    const float* Wq       = (const float*)d_in[7];   // [1024,1024]
    const float* bq       = (const float*)d_in[8];   // [1024]
    const int*   length   = (const int*)d_in[9];     // [64]
    const int*   plen     = (const int*)d_in[10];    // [64]
    float* out = (float*)d_out;

    float *gi, *q, *scores, *attnT;
    cudaGetSymbolAddress((void**)&gi,     g_gi);
    cudaGetSymbolAddress((void**)&q,      g_q);
    cudaGetSymbolAddress((void**)&scores, g_scores);
    cudaGetSymbolAddress((void**)&attnT,  g_attnT);

    cudaFuncSetAttribute(recurrence2_kernel,
                         cudaFuncAttributeMaxDynamicSharedMemorySize, SM_TOTAL);

    // 1) gi = incoming @ W_ih^T + b_ih : [16384, 3072], K=1024
    gemm_nt_kernel<<<dim3(128, 24, 1), 256>>>(
        incoming, W_ih, b_ih, gi, 1024, 1024, 1024, 3072, 0, 0, 0);

    // 2) recurrence: one persistent kernel (barrier reset + init h)
    init_kernel<<<64, 256>>>(h_init);
    recurrence2_kernel<<<GRID_P, 256, SM_TOTAL>>>(
        W_hh, gi, b_hh, length, out + HS_OFF);

    // 3) queries = hs_h @ Wq^T + bq : [16384, 1024], A stride 2048
    gemm_nt_kernel<<<dim3(128, 8, 1), 256>>>(
        out + HS_OFF, Wq, bq, q, 1024, 2048, 1024, 1024, 0, 0, 0);

    // 4) scores[b][s][l] = q[s,b,:] . post[l,b,:]  (batched over b)
    gemm_nt_kernel<<<dim3(2, 2, 64), 256>>>(
        q, post, (const float*)0, scores, 1024,
        (long long)BATCH * PSZ, (long long)BATCH * PSZ, PLEN,
        PSZ, PSZ, (long long)S_LEN * PLEN);

    // 5) masked softmax over l; writes attnT and the attn output block
    softmax_kernel<<<dim3(256, 64), 256>>>(scores, plen, attnT, out + ATTN_OFF);

    // 6) context[s][b][p] = attnT[b][s][:] @ post[:,b,:]  (batched over b)
    gemm_nn_kernel<<<dim3(2, 8, 64), 256>>>(
        attnT, post, out + HS_OFF + 1024, PLEN,
        PLEN, (long long)BATCH * PSZ, (long long)BATCH * 2048,
        (long long)S_LEN * PLEN, PSZ, 2048);

    // 7) h_last = hs[255, :, :1024]
    hlast_kernel<<<64, 256>>>(out + HS_OFF + (long long)255 * BATCH * 2048, out);
}

// round 14
// speedup vs baseline: 1.6309x; 1.0379x over previous
#include <cuda_runtime.h>
#include <math.h>
#include <stdint.h>

// Problem shapes (fixed)
#define S_LEN 256
#define BATCH 64
#define HSZ   1024
#define H3    3072
#define PLEN  256
#define PSZ   1024
// Output layout: [h_last (64*1024) | hs (256*64*2048) | attn (256*256*64)]
#define HS_OFF   65536
#define ATTN_OFF 33619968
#define NEGV -1000000000.0f

// Persistent recurrence config
#define GRID_P 128          // 128 CTAs, each owns 8 hidden units (all 3 gates)
// dynamic smem layout (bytes)
#define SM_W    0           // Wsm[24][1024] floats = 98304
#define SM_HS   98304       // Hs[2][4][64][36] floats = 73728
#define SM_RED  172032      // red[4][24][66] floats = 25344
#define SM_TOTAL 197376
#define HSBUF   36864       // one Hs buffer (4*64*36*4)

typedef unsigned long long ull;

// ---------------- device scratch (no runtime allocation allowed) -----------
__device__ float g_gi[(size_t)S_LEN * BATCH * H3];       // 201 MB
__device__ float g_q[(size_t)S_LEN * BATCH * PSZ];       //  64 MB
__device__ float g_scores[(size_t)BATCH * S_LEN * PLEN]; //  16 MB
__device__ float g_attnT[(size_t)BATCH * S_LEN * PLEN];  //  16 MB
__device__ float g_hbuf[2][BATCH][HSZ];                  // 512 KB ping-pong
__device__ ull   g_bar;

// ---------------- packed fp32x2 helpers (Blackwell FFMA2 path) -------------
__device__ __forceinline__ ull pk2(float lo, float hi) {
    ull r;
    asm("mov.b64 %0, {%1, %2};" : "=l"(r) : "f"(lo), "f"(hi));
    return r;
}
__device__ __forceinline__ float2 upk2(ull v) {
    float2 r;
    asm("mov.b64 {%0, %1}, %2;" : "=f"(r.x), "=f"(r.y) : "l"(v));
    return r;
}
__device__ __forceinline__ void f2fma(ull &c, ull a, ull b) {
    asm("fma.rn.f32x2 %0, %1, %2, %0;" : "+l"(c) : "l"(a), "l"(b));
}

// ---------------- cp.async helpers ----------------------------------------
__device__ __forceinline__ void cp16(uint32_t dst, const void* src) {
    asm volatile("cp.async.cg.shared.global [%0], [%1], 16;\n"
                 :: "r"(dst), "l"(src) : "memory");
}
#define CP_COMMIT() asm volatile("cp.async.commit_group;\n" ::: "memory")
#define CP_WAIT1()  asm volatile("cp.async.wait_group 1;\n" ::: "memory")

// ---------------- grid-wide barrier ----------------------------------------
__device__ __forceinline__ void grid_bar() {
    __threadfence();          // release my writes
    __syncthreads();
    if (threadIdx.x == 0) {
        ull t = atomicAdd(&g_bar, 1ULL) + 1ULL;
        ull target = ((t + GRID_P - 1) / GRID_P) * GRID_P;
        while (*((volatile ull*)&g_bar) < target) { }
        __threadfence();      // acquire
    }
    __syncthreads();
}

// ===========================================================================
// init: reset barrier counter, broadcast h_init into ping buffer 0
// ===========================================================================
__global__ void init_kernel(const float* __restrict__ h_init) {
    if (blockIdx.x == 0 && threadIdx.x == 0) g_bar = 0ULL;
    int b = blockIdx.x;  // 64 blocks
    ((float4*)&g_hbuf[0][b][0])[threadIdx.x] = ((const float4*)h_init)[threadIdx.x];
}

// ===========================================================================
// Persistent recurrence kernel v2.1.  grid=128, 256 threads, ~193 KB smem.
// CTA c owns hidden units j = c*8..c*8+7 -> W rows {j, 1024+j, 2048+j} (24).
// v2.1: phase-B operands (gi, h_prev) prefetched at step top, before phase A.
// ===========================================================================
__global__ void __launch_bounds__(256) recurrence2_kernel(
    const float* __restrict__ W, const float* __restrict__ gi,
    const float* __restrict__ bhh, const int* __restrict__ length,
    float* __restrict__ hs_out)
{
    extern __shared__ __align__(16) char smem[];
    float* Wsm = (float*)(smem + SM_W);     // [24][1024]
    float* red = (float*)(smem + SM_RED);   // [4][24][66]
    uint32_t sb;
    asm("{ .reg .u64 t; cvta.to.shared.u64 t, %1; cvt.u32.u64 %0, t; }"
        : "=r"(sb) : "l"(smem));
    const uint32_t hs_u32 = sb + SM_HS;

    const int c = blockIdx.x, tid = threadIdx.x;
    const int w = tid >> 5, lane = tid & 31;
    const int ks = w >> 1, rg = w & 1;      // k-slice 0..3, row-half 0..1
    const int b0 = lane, b1 = lane + 32;

    // ---- load W rows (gathered {r,z,n} x 8 units) once, coalesced ----
    for (int idx = tid; idx < 24 * 256; idx += 256) {
        int u = idx >> 8, f4 = idx & 255;
        long long grow = (long long)(u >> 3) * 1024 + c * 8 + (u & 7);
        *(float4*)&Wsm[u * 1024 + f4 * 4] =
            *(const float4*)&W[grow * 1024 + f4 * 4];
    }

    // ---- gate-phase constants (j fixed per thread; two batches) ----
    const int j  = tid & 7;
    const int bA = tid >> 3;        // 0..31
    const int bB = bA + 32;
    const float br = bhh[c * 8 + j];
    const float bz = bhh[HSZ + c * 8 + j];
    const float bn = bhh[2 * HSZ + c * 8 + j];
    const int lenA = length[bA], lenB = length[bB];

    __syncthreads();

    int p = 0;
    for (int s = 0; s < S_LEN; s++) {
        const float* hsrc = &g_hbuf[p][0][0];

        // ---- prefetch ALL phase-B operands (independent of phase A) ----
        const float* giA = gi + ((long long)s * BATCH + bA) * H3 + c * 8 + j;
        const float* giB = gi + ((long long)s * BATCH + bB) * H3 + c * 8 + j;
        float girA = __ldg(giA), gizA = __ldg(giA + HSZ), ginA = __ldg(giA + 2 * HSZ);
        float girB = __ldg(giB), gizB = __ldg(giB + HSZ), ginB = __ldg(giB + 2 * HSZ);
        float hpA = g_hbuf[p][bA][c * 8 + j];
        float hpB = g_hbuf[p][bB][c * 8 + j];

        // prologue: stage chunks 0,1
#pragma unroll
        for (int cj = 0; cj < 2; cj++) {
#pragma unroll
            for (int i = 0; i < 8; i++) {
                int idx = tid + i * 256;
                int b = idx >> 5, kss = (idx >> 3) & 3, f4 = idx & 7;
                cp16(hs_u32 + cj * HSBUF + kss * 9216 + b * 144 + f4 * 16,
                     hsrc + (long long)b * 1024 + kss * 256 + cj * 32 + f4 * 4);
            }
            CP_COMMIT();
        }

        ull acc[12][2];
#pragma unroll
        for (int r = 0; r < 12; r++) { acc[r][0] = 0ull; acc[r][1] = 0ull; }

        for (int cj = 0; cj < 8; cj++) {
            CP_WAIT1();
            __syncthreads();
            const char* hb = smem + SM_HS + (cj & 1) * HSBUF + ks * 9216;
#pragma unroll
            for (int half = 0; half < 2; half++) {
                const int kk0 = half * 16;
                ull hA[8], hB[8];
                const ull* hpA2 = (const ull*)(hb + b0 * 144 + kk0 * 4);
                const ull* hpB2 = (const ull*)(hb + b1 * 144 + kk0 * 4);
#pragma unroll
                for (int i = 0; i < 8; i++) { hA[i] = hpA2[i]; hB[i] = hpB2[i]; }
#pragma unroll
                for (int r = 0; r < 12; r++) {
                    const ull* wp = (const ull*)&Wsm[(rg * 12 + r) * 1024 +
                                                     ks * 256 + cj * 32 + kk0];
#pragma unroll
                    for (int i = 0; i < 8; i++) {
                        ull wv = wp[i];
                        f2fma(acc[r][0], wv, hA[i]);
                        f2fma(acc[r][1], wv, hB[i]);
                    }
                }
            }
            __syncthreads();
            if (cj + 2 < 8) {
#pragma unroll
                for (int i = 0; i < 8; i++) {
                    int idx = tid + i * 256;
                    int b = idx >> 5, kss = (idx >> 3) & 3, f4 = idx & 7;
                    cp16(hs_u32 + (cj & 1) * HSBUF + kss * 9216 + b * 144 + f4 * 16,
                         hsrc + (long long)b * 1024 + kss * 256 + (cj + 2) * 32 + f4 * 4);
                }
            }
            CP_COMMIT();
        }

        // ---- reduce: write per-slice partials (pair-summed) ----
#pragma unroll
        for (int r = 0; r < 12; r++) {
            float2 e0 = upk2(acc[r][0]);
            float2 e1 = upk2(acc[r][1]);
            red[(ks * 24 + rg * 12 + r) * 66 + b0] = e0.x + e0.y;
            red[(ks * 24 + rg * 12 + r) * 66 + b1] = e1.x + e1.y;
        }
        __syncthreads();

        // ---- phase B: gates for (j, bA) and (j, bB), CTA-local ----
        {
            float srA = 0, szA = 0, snA = 0, srB = 0, szB = 0, snB = 0;
#pragma unroll
            for (int k4 = 0; k4 < 4; k4++) {
                srA += red[(k4 * 24 + j) * 66 + bA];
                srB += red[(k4 * 24 + j) * 66 + bB];
                szA += red[(k4 * 24 + 8 + j) * 66 + bA];
                szB += red[(k4 * 24 + 8 + j) * 66 + bB];
                snA += red[(k4 * 24 + 16 + j) * 66 + bA];
                snB += red[(k4 * 24 + 16 + j) * 66 + bB];
            }
            float rA = 1.f / (1.f + expf(-(girA + srA + br)));
            float zA = 1.f / (1.f + expf(-(gizA + szA + bz)));
            float nA = tanhf(ginA + rA * (snA + bn));
            float kA = (s < lenA) ? 1.f : 0.f;
            float hA2 = (nA + zA * (hpA - nA)) * kA;

            float rB = 1.f / (1.f + expf(-(girB + srB + br)));
            float zB = 1.f / (1.f + expf(-(gizB + szB + bz)));
            float nB = tanhf(ginB + rB * (snB + bn));
            float kB = (s < lenB) ? 1.f : 0.f;
            float hB2 = (nB + zB * (hpB - nB)) * kB;

            g_hbuf[p ^ 1][bA][c * 8 + j] = hA2;
            g_hbuf[p ^ 1][bB][c * 8 + j] = hB2;
            hs_out[((long long)s * BATCH + bA) * 2048 + c * 8 + j] = hA2;
            hs_out[((long long)s * BATCH + bB) * 2048 + c * 8 + j] = hB2;
        }
        grid_bar();
        p ^= 1;
    }
}

// ===========================================================================
// C[M,N] = A[M,K] * B[N,K]^T (+bias). A,B K-contiguous. 128x128 tile, BK=8,
// 256 threads, 8x8 per-thread microtile, fp32x2 accumulation.
// v2: register-prefetch software pipeline (next k-tile loads issue before
// the FFMA2 block of the current tile).
// ===========================================================================
__global__ void __launch_bounds__(256, 2) gemm_nt_kernel(
    const float* __restrict__ A, const float* __restrict__ B,
    const float* __restrict__ bias, float* __restrict__ C,
    int K, long long lda, long long ldb, long long ldc,
    long long bsA, long long bsB, long long bsC)
{
    __shared__ __align__(16) float As[8][128];
    __shared__ __align__(16) float Bs[8][128];
    long long bz = blockIdx.z;
    A += bz * bsA; B += bz * bsB; C += bz * bsC;
    int m0 = blockIdx.x * 128, n0 = blockIdx.y * 128;
    int tid = threadIdx.x;
    int lr = tid >> 1, lk = (tid & 1) * 4;
    const float* aP = A + (long long)(m0 + lr) * lda + lk;
    const float* bP = B + (long long)(n0 + lr) * ldb + lk;
    int ty = tid >> 4, tx = tid & 15;

    ull acc[8][4];
#pragma unroll
    for (int i = 0; i < 8; i++)
#pragma unroll
        for (int j = 0; j < 4; j++) acc[i][j] = 0ull;

    float4 av = *(const float4*)aP;
    float4 bv = *(const float4*)bP;

    for (int k0 = 0; k0 < K; k0 += 8) {
        __syncthreads();
        As[lk + 0][lr] = av.x; As[lk + 1][lr] = av.y;
        As[lk + 2][lr] = av.z; As[lk + 3][lr] = av.w;
        Bs[lk + 0][lr] = bv.x; Bs[lk + 1][lr] = bv.y;
        Bs[lk + 2][lr] = bv.z; Bs[lk + 3][lr] = bv.w;
        __syncthreads();
        aP += 8; bP += 8;
        if (k0 + 8 < K) {               // prefetch next tile (hidden by FFMA2)
            av = *(const float4*)aP;
            bv = *(const float4*)bP;
        }
#pragma unroll
        for (int k = 0; k < 8; k++) {
            float4 a0 = *(const float4*)&As[k][ty * 8];
            float4 a1 = *(const float4*)&As[k][ty * 8 + 4];
            ull b0 = *(const ull*)&Bs[k][tx * 8];
            ull b1 = *(const ull*)&Bs[k][tx * 8 + 2];
            ull b2 = *(const ull*)&Bs[k][tx * 8 + 4];
            ull b3 = *(const ull*)&Bs[k][tx * 8 + 6];
            float a[8] = {a0.x, a0.y, a0.z, a0.w, a1.x, a1.y, a1.z, a1.w};
#pragma unroll
            for (int i = 0; i < 8; i++) {
                ull a2 = pk2(a[i], a[i]);
                f2fma(acc[i][0], a2, b0);
                f2fma(acc[i][1], a2, b1);
                f2fma(acc[i][2], a2, b2);
                f2fma(acc[i][3], a2, b3);
            }
        }
    }

    float bb[8];
#pragma unroll
    for (int jj = 0; jj < 8; jj++) bb[jj] = bias ? bias[n0 + tx * 8 + jj] : 0.f;
#pragma unroll
    for (int i = 0; i < 8; i++) {
        float2 p0 = upk2(acc[i][0]), p1 = upk2(acc[i][1]);
        float2 p2 = upk2(acc[i][2]), p3 = upk2(acc[i][3]);
        float4 v0 = make_float4(p0.x + bb[0], p0.y + bb[1], p1.x + bb[2], p1.y + bb[3]);
        float4 v1 = make_float4(p2.x + bb[4], p2.y + bb[5], p3.x + bb[6], p3.y + bb[7]);
        float* cp = C + (long long)(m0 + ty * 8 + i) * ldc + n0 + tx * 8;
        *(float4*)cp = v0;
        *(float4*)(cp + 4) = v1;
    }
}

// ===========================================================================
// C[M,N] = A[M,K] * B[K,N]  (A K-contig rows, B N-contig rows).
// v2: same register-prefetch pipeline.
// ===========================================================================
__global__ void __launch_bounds__(256, 2) gemm_nn_kernel(
    const float* __restrict__ A, const float* __restrict__ B,
    float* __restrict__ C,
    int K, long long lda, long long ldb, long long ldc,
    long long bsA, long long bsB, long long bsC)
{
    __shared__ __align__(16) float As[8][128];
    __shared__ __align__(16) float Bs[8][128];
    long long bz = blockIdx.z;
    A += bz * bsA; B += bz * bsB; C += bz * bsC;
    int m0 = blockIdx.x * 128, n0 = blockIdx.y * 128;
    int tid = threadIdx.x;
    int lr = tid >> 1, lk = (tid & 1) * 4;
    const float* aP = A + (long long)(m0 + lr) * lda + lk;
    int bRow = tid >> 5, bCol = (tid & 31) * 4;
    const float* bP = B + (long long)bRow * ldb + n0 + bCol;
    int ty = tid >> 4, tx = tid & 15;

    ull acc[8][4];
#pragma unroll
    for (int i = 0; i < 8; i++)
#pragma unroll
        for (int j = 0; j < 4; j++) acc[i][j] = 0ull;

    float4 av = *(const float4*)aP;
    float4 bv = *(const float4*)bP;

    for (int k0 = 0; k0 < K; k0 += 8) {
        __syncthreads();
        As[lk + 0][lr] = av.x; As[lk + 1][lr] = av.y;
        As[lk + 2][lr] = av.z; As[lk + 3][lr] = av.w;
        *(float4*)&Bs[bRow][bCol] = bv;
        __syncthreads();
        aP += 8; bP += 8 * ldb;
        if (k0 + 8 < K) {
            av = *(const float4*)aP;
            bv = *(const float4*)bP;
        }
#pragma unroll
        for (int k = 0; k < 8; k++) {
            float4 a0 = *(const float4*)&As[k][ty * 8];
            float4 a1 = *(const float4*)&As[k][ty * 8 + 4];
            ull b0 = *(const ull*)&Bs[k][tx * 8];
            ull b1 = *(const ull*)&Bs[k][tx * 8 + 2];
            ull b2 = *(const ull*)&Bs[k][tx * 8 + 4];
            ull b3 = *(const ull*)&Bs[k][tx * 8 + 6];
            float a[8] = {a0.x, a0.y, a0.z, a0.w, a1.x, a1.y, a1.z, a1.w};
#pragma unroll
            for (int i = 0; i < 8; i++) {
                ull a2 = pk2(a[i], a[i]);
                f2fma(acc[i][0], a2, b0);
                f2fma(acc[i][1], a2, b1);
                f2fma(acc[i][2], a2, b2);
                f2fma(acc[i][3], a2, b3);
            }
        }
    }

#pragma unroll
    for (int i = 0; i < 8; i++) {
        float2 p0 = upk2(acc[i][0]), p1 = upk2(acc[i][1]);
        float2 p2 = upk2(acc[i][2]), p3 = upk2(acc[i][3]);
        float* cp = C + (long long)(m0 + ty * 8 + i) * ldc + n0 + tx * 8;
        *(float4*)cp = make_float4(p0.x, p0.y, p1.x, p1.y);
        *(float4*)(cp + 4) = make_float4(p2.x, p2.y, p3.x, p3.y);
    }
}

// ===========================================================================
// Masked softmax over l (PLEN) per (s, b). Writes attnT[b][s][l] and attn out.
// ===========================================================================
__global__ void __launch_bounds__(256) softmax_kernel(
    const float* __restrict__ scores, const int* __restrict__ post_length,
    float* __restrict__ attnT, float* __restrict__ attn_out)
{
    __shared__ float sm[256];
    int s = blockIdx.x, b = blockIdx.y, l = threadIdx.x;
    float sc = scores[((long long)b * S_LEN + s) * PLEN + l];
    if (l >= post_length[b]) sc = NEGV;
    sm[l] = sc; __syncthreads();
    for (int o = 128; o > 0; o >>= 1) {
        if (l < o) sm[l] = fmaxf(sm[l], sm[l + o]);
        __syncthreads();
    }
    float mx = sm[0]; __syncthreads();
    float e = expf(sc - mx);
    sm[l] = e; __syncthreads();
    for (int o = 128; o > 0; o >>= 1) {
        if (l < o) sm[l] += sm[l + o];
        __syncthreads();
    }
    float a = e / sm[0];
    attnT[((long long)b * S_LEN + s) * PLEN + l] = a;
    attn_out[(long long)s * (PLEN * BATCH) + (long long)l * BATCH + b] = a;
}

// h_last = hs[255][:, :1024]
__global__ void hlast_kernel(const float* __restrict__ src, float* __restrict__ dst)
{
    int b = blockIdx.x, t = threadIdx.x;
    float4 v = *(const float4*)(src + (long long)b * 2048 + t * 4);
    *(float4*)(dst + (long long)b * 1024 + t * 4) = v;
}

// ===========================================================================
extern "C" void kernel_launch(void* const* d_in, const int* in_sizes, int n_in,
                              void* d_out, int out_size)
{
    const float* incoming = (const float*)d_in[0];   // [256,64,1024]
    const float* post     = (const float*)d_in[1];   // [256,64,1024]
    const float* h_init   = (const float*)d_in[2];   // [1,1,1024]
    const float* W_ih     = (const float*)d_in[3];   // [3072,1024]
    const float* W_hh     = (const float*)d_in[4];   // [3072,1024]
    const float* b_ih     = (const float*)d_in[5];   // [3072]
    const float* b_hh     = (const float*)d_in[6];   // [3072]
    const float* Wq       = (const float*)d_in[7];   // [1024,1024]
    const float* bq       = (const float*)d_in[8];   // [1024]
    const int*   length   = (const int*)d_in[9];     // [64]
    const int*   plen     = (const int*)d_in[10];    // [64]
    float* out = (float*)d_out;

    float *gi, *q, *scores, *attnT;
    cudaGetSymbolAddress((void**)&gi,     g_gi);
    cudaGetSymbolAddress((void**)&q,      g_q);
    cudaGetSymbolAddress((void**)&scores, g_scores);
    cudaGetSymbolAddress((void**)&attnT,  g_attnT);

    cudaFuncSetAttribute(recurrence2_kernel,
                         cudaFuncAttributeMaxDynamicSharedMemorySize, SM_TOTAL);

    // 1) gi = incoming @ W_ih^T + b_ih : [16384, 3072], K=1024
    gemm_nt_kernel<<<dim3(128, 24, 1), 256>>>(
        incoming, W_ih, b_ih, gi, 1024, 1024, 1024, 3072, 0, 0, 0);

    // 2) recurrence: one persistent kernel (barrier reset + init h)
    init_kernel<<<64, 256>>>(h_init);
    recurrence2_kernel<<<GRID_P, 256, SM_TOTAL>>>(
        W_hh, gi, b_hh, length, out + HS_OFF);

    // 3) queries = hs_h @ Wq^T + bq : [16384, 1024], A stride 2048
    gemm_nt_kernel<<<dim3(128, 8, 1), 256>>>(
        out + HS_OFF, Wq, bq, q, 1024, 2048, 1024, 1024, 0, 0, 0);

    // 4) scores[b][s][l] = q[s,b,:] . post[l,b,:]  (batched over b)
    gemm_nt_kernel<<<dim3(2, 2, 64), 256>>>(
        q, post, (const float*)0, scores, 1024,
        (long long)BATCH * PSZ, (long long)BATCH * PSZ, PLEN,
        PSZ, PSZ, (long long)S_LEN * PLEN);

    // 5) masked softmax over l; writes attnT and the attn output block
    softmax_kernel<<<dim3(256, 64), 256>>>(scores, plen, attnT, out + ATTN_OFF);

    // 6) context[s][b][p] = attnT[b][s][:] @ post[:,b,:]  (batched over b)
    gemm_nn_kernel<<<dim3(2, 8, 64), 256>>>(
        attnT, post, out + HS_OFF + 1024, PLEN,
        PLEN, (long long)BATCH * PSZ, (long long)BATCH * 2048,
        (long long)S_LEN * PLEN, PSZ, 2048);

    // 7) h_last = hs[255, :, :1024]
    hlast_kernel<<<64, 256>>>(out + HS_OFF + (long long)255 * BATCH * 2048, out);
}

// round 16
// speedup vs baseline: 1.7077x; 1.0471x over previous
#include <cuda_runtime.h>
#include <math.h>
#include <stdint.h>

// Problem shapes (fixed)
#define S_LEN 256
#define BATCH 64
#define HSZ   1024
#define H3    3072
#define PLEN  256
#define PSZ   1024
// Output layout: [h_last (64*1024) | hs (256*64*2048) | attn (256*256*64)]
#define HS_OFF   65536
#define ATTN_OFF 33619968
#define NEGV -1000000000.0f

// Persistent recurrence config
#define GRID_P 128          // 128 CTAs, each owns 8 hidden units (all 3 gates)
// dynamic smem layout (bytes)
#define SM_W    0           // Wsm[24][1024] floats            = 98304
#define SM_HS   98304       // Hs[2][4 kss][16 k2][64 b] ull   = 65536
#define SM_RED  163840      // red[4][24][66] floats           = 25344
#define SM_TOTAL 189184
#define HSBUF   32768       // one Hs buffer (4*16*64*8)

typedef unsigned long long ull;

// ---------------- device scratch (no runtime allocation allowed) -----------
__device__ float g_gi[(size_t)S_LEN * BATCH * H3];       // 201 MB
__device__ float g_q[(size_t)S_LEN * BATCH * PSZ];       //  64 MB
__device__ float g_scores[(size_t)BATCH * S_LEN * PLEN]; //  16 MB
__device__ float g_attnT[(size_t)BATCH * S_LEN * PLEN];  //  16 MB
__device__ ull   g_hbufT[2][512][64];                    // 512 KB, [p][k/2][b] packed pairs
__device__ ull   g_bar;

// ---------------- packed fp32x2 helpers (Blackwell FFMA2 path) -------------
__device__ __forceinline__ ull pk2(float lo, float hi) {
    ull r;
    asm("mov.b64 %0, {%1, %2};" : "=l"(r) : "f"(lo), "f"(hi));
    return r;
}
__device__ __forceinline__ float2 upk2(ull v) {
    float2 r;
    asm("mov.b64 {%0, %1}, %2;" : "=f"(r.x), "=f"(r.y) : "l"(v));
    return r;
}
__device__ __forceinline__ void f2fma(ull &c, ull a, ull b) {
    asm("fma.rn.f32x2 %0, %1, %2, %0;" : "+l"(c) : "l"(a), "l"(b));
}

// ---------------- cp.async helpers ----------------------------------------
__device__ __forceinline__ void cp16(uint32_t dst, const void* src) {
    asm volatile("cp.async.cg.shared.global [%0], [%1], 16;\n"
                 :: "r"(dst), "l"(src) : "memory");
}
#define CP_COMMIT() asm volatile("cp.async.commit_group;\n" ::: "memory")
#define CP_WAIT1()  asm volatile("cp.async.wait_group 1;\n" ::: "memory")

// ---------------- grid-wide barrier ----------------------------------------
__device__ __forceinline__ void grid_bar() {
    __threadfence();          // release my writes
    __syncthreads();
    if (threadIdx.x == 0) {
        ull t = atomicAdd(&g_bar, 1ULL) + 1ULL;
        ull target = ((t + GRID_P - 1) / GRID_P) * GRID_P;
        while (*((volatile ull*)&g_bar) < target) { }
        __threadfence();      // acquire
    }
    __syncthreads();
}

// ===========================================================================
// init: reset barrier counter, broadcast h_init into transposed ping buffer 0
// grid 64 (batch), 512 threads (k2)
// ===========================================================================
__global__ void init_kernel(const float* __restrict__ h_init) {
    if (blockIdx.x == 0 && threadIdx.x == 0) g_bar = 0ULL;
    int b = blockIdx.x, k2 = threadIdx.x;
    g_hbufT[0][k2][b] = pk2(h_init[2 * k2], h_init[2 * k2 + 1]);
}

// ===========================================================================
// Persistent recurrence kernel v3.  grid=128, 256 threads, ~185 KB smem.
// CTA c owns hidden units j = c*8..c*8+7 -> W rows {j, 1024+j, 2048+j} (24).
// v3: h in transposed packed layout [k2][b] (conflict-free LDS, N=1),
//     W broadcast LDS.128, phase B computes 2 adjacent units per thread and
//     writes the packed h pair directly.
// ===========================================================================
__global__ void __launch_bounds__(256) recurrence3_kernel(
    const float* __restrict__ W, const float* __restrict__ gi,
    const float* __restrict__ bhh, const int* __restrict__ length,
    float* __restrict__ hs_out)
{
    extern __shared__ __align__(16) char smem[];
    float* Wsm = (float*)(smem + SM_W);     // [24][1024]
    float* red = (float*)(smem + SM_RED);   // [4][24][66]
    uint32_t sb;
    asm("{ .reg .u64 t; cvta.to.shared.u64 t, %1; cvt.u32.u64 %0, t; }"
        : "=r"(sb) : "l"(smem));
    const uint32_t hs_u32 = sb + SM_HS;

    const int c = blockIdx.x, tid = threadIdx.x;
    const int w = tid >> 5, lane = tid & 31;
    const int ks = w >> 1, rg = w & 1;      // k-slice 0..3 (256k), row-half 0..1

    // ---- load W rows (gathered {r,z,n} x 8 units) once, coalesced ----
    for (int idx = tid; idx < 24 * 256; idx += 256) {
        int u = idx >> 8, f4 = idx & 255;
        long long grow = (long long)(u >> 3) * 1024 + c * 8 + (u & 7);
        *(float4*)&Wsm[u * 1024 + f4 * 4] =
            *(const float4*)&W[grow * 1024 + f4 * 4];
    }

    // ---- phase-B mapping: 2 adjacent units x 1 batch per thread ----
    const int j2 = tid >> 6;        // 0..3 (unit pair)
    const int gb = tid & 63;        // batch
    const float2 brv = *(const float2*)&bhh[c * 8 + j2 * 2];
    const float2 bzv = *(const float2*)&bhh[HSZ + c * 8 + j2 * 2];
    const float2 bnv = *(const float2*)&bhh[2 * HSZ + c * 8 + j2 * 2];
    const int mylen = length[gb];

    __syncthreads();

    int p = 0;
    for (int s = 0; s < S_LEN; s++) {
        const ull* hsrc = &g_hbufT[p][0][0];

        // ---- prefetch phase-B operands (independent of phase A) ----
        const float* gib = gi + ((long long)s * BATCH + gb) * H3 + c * 8 + j2 * 2;
        float2 gir = *(const float2*)gib;
        float2 giz = *(const float2*)(gib + HSZ);
        float2 gin = *(const float2*)(gib + 2 * HSZ);
        ull hpq = g_hbufT[p][c * 4 + j2][gb];

        // ---- prologue: stage chunks 0,1 (32 KB each, contiguous copy) ----
#pragma unroll
        for (int cj = 0; cj < 2; cj++) {
#pragma unroll
            for (int i = 0; i < 8; i++) {
                int idx = tid + i * 256;                    // 0..2047
                int kss = idx >> 9, k2l = (idx >> 5) & 15, bp = idx & 31;
                cp16(hs_u32 + cj * HSBUF + kss * 8192 + k2l * 512 + bp * 16,
                     hsrc + (kss * 128 + cj * 16 + k2l) * 64 + bp * 2);
            }
            CP_COMMIT();
        }

        ull acc[12][2];
#pragma unroll
        for (int r = 0; r < 12; r++) { acc[r][0] = 0ull; acc[r][1] = 0ull; }

        for (int cj = 0; cj < 8; cj++) {
            CP_WAIT1();
            __syncthreads();
            const char* hb = smem + SM_HS + (cj & 1) * HSBUF + ks * 8192;
#pragma unroll
            for (int kp = 0; kp < 8; kp++) {                // 2 k2 (4 k) per kp
                ull hA0 = *(const ull*)(hb + (kp * 2 + 0) * 512 + lane * 8);
                ull hA1 = *(const ull*)(hb + (kp * 2 + 1) * 512 + lane * 8);
                ull hB0 = *(const ull*)(hb + (kp * 2 + 0) * 512 + 256 + lane * 8);
                ull hB1 = *(const ull*)(hb + (kp * 2 + 1) * 512 + 256 + lane * 8);
#pragma unroll
                for (int r = 0; r < 12; r++) {
                    ulonglong2 wv = *(const ulonglong2*)
                        &Wsm[(rg * 12 + r) * 1024 + ks * 256 + cj * 32 + kp * 4];
                    f2fma(acc[r][0], wv.x, hA0);
                    f2fma(acc[r][0], wv.y, hA1);
                    f2fma(acc[r][1], wv.x, hB0);
                    f2fma(acc[r][1], wv.y, hB1);
                }
            }
            __syncthreads();        // all warps done reading buffer (cj&1)
            if (cj + 2 < 8) {
#pragma unroll
                for (int i = 0; i < 8; i++) {
                    int idx = tid + i * 256;
                    int kss = idx >> 9, k2l = (idx >> 5) & 15, bp = idx & 31;
                    cp16(hs_u32 + (cj & 1) * HSBUF + kss * 8192 + k2l * 512 + bp * 16,
                         hsrc + (kss * 128 + (cj + 2) * 16 + k2l) * 64 + bp * 2);
                }
            }
            CP_COMMIT();
        }

        // ---- reduce: per-slice partials (pair-summed over even/odd k) ----
#pragma unroll
        for (int r = 0; r < 12; r++) {
            int u = rg * 12 + r;
            float2 e0 = upk2(acc[r][0]);
            float2 e1 = upk2(acc[r][1]);
            red[(ks * 24 + u) * 66 + lane]      = e0.x + e0.y;
            red[(ks * 24 + u) * 66 + lane + 32] = e1.x + e1.y;
        }
        __syncthreads();

        // ---- phase B: gates for units (j2*2, j2*2+1) of batch gb ----
        {
            float sr0 = 0, sr1 = 0, sz0 = 0, sz1 = 0, sn0 = 0, sn1 = 0;
#pragma unroll
            for (int k4 = 0; k4 < 4; k4++) {
                int base = k4 * 24;
                sr0 += red[(base + j2 * 2 + 0) * 66 + gb];
                sr1 += red[(base + j2 * 2 + 1) * 66 + gb];
                sz0 += red[(base + 8 + j2 * 2 + 0) * 66 + gb];
                sz1 += red[(base + 8 + j2 * 2 + 1) * 66 + gb];
                sn0 += red[(base + 16 + j2 * 2 + 0) * 66 + gb];
                sn1 += red[(base + 16 + j2 * 2 + 1) * 66 + gb];
            }
            float2 hp = upk2(hpq);
            float keep = (s < mylen) ? 1.f : 0.f;

            float r0 = 1.f / (1.f + expf(-(gir.x + sr0 + brv.x)));
            float r1 = 1.f / (1.f + expf(-(gir.y + sr1 + brv.y)));
            float z0 = 1.f / (1.f + expf(-(giz.x + sz0 + bzv.x)));
            float z1 = 1.f / (1.f + expf(-(giz.y + sz1 + bzv.y)));
            float n0 = tanhf(gin.x + r0 * (sn0 + bnv.x));
            float n1 = tanhf(gin.y + r1 * (sn1 + bnv.y));
            float h0 = (n0 + z0 * (hp.x - n0)) * keep;
            float h1 = (n1 + z1 * (hp.y - n1)) * keep;

            g_hbufT[p ^ 1][c * 4 + j2][gb] = pk2(h0, h1);
            *(float2*)&hs_out[((long long)s * BATCH + gb) * 2048 + c * 8 + j2 * 2] =
                make_float2(h0, h1);
        }
        grid_bar();
        p ^= 1;
    }
}

// ===========================================================================
// C[M,N] = A[M,K] * B[N,K]^T (+bias). A,B K-contiguous. 128x128 tile, BK=8,
// 256 threads, 8x8 per-thread microtile, fp32x2 accumulation.
// v3: double-buffered smem, ONE __syncthreads per k-tile; stores overlap
// the other warps' compute.
// ===========================================================================
__global__ void __launch_bounds__(256, 2) gemm_nt_kernel(
    const float* __restrict__ A, const float* __restrict__ B,
    const float* __restrict__ bias, float* __restrict__ C,
    int K, long long lda, long long ldb, long long ldc,
    long long bsA, long long bsB, long long bsC)
{
    __shared__ __align__(16) float As[2][8][128];
    __shared__ __align__(16) float Bs[2][8][128];
    long long bz = blockIdx.z;
    A += bz * bsA; B += bz * bsB; C += bz * bsC;
    int m0 = blockIdx.x * 128, n0 = blockIdx.y * 128;
    int tid = threadIdx.x;
    int lr = tid >> 1, lk = (tid & 1) * 4;
    const float* aP = A + (long long)(m0 + lr) * lda + lk;
    const float* bP = B + (long long)(n0 + lr) * ldb + lk;
    int ty = tid >> 4, tx = tid & 15;

    ull acc[8][4];
#pragma unroll
    for (int i = 0; i < 8; i++)
#pragma unroll
        for (int j = 0; j < 4; j++) acc[i][j] = 0ull;

    // tile 0 -> buf 0
    {
        float4 av = *(const float4*)aP;
        float4 bv = *(const float4*)bP;
        As[0][lk + 0][lr] = av.x; As[0][lk + 1][lr] = av.y;
        As[0][lk + 2][lr] = av.z; As[0][lk + 3][lr] = av.w;
        Bs[0][lk + 0][lr] = bv.x; Bs[0][lk + 1][lr] = bv.y;
        Bs[0][lk + 2][lr] = bv.z; Bs[0][lk + 3][lr] = bv.w;
    }

    int cur = 0;
    for (int k0 = 0; k0 < K; k0 += 8) {
        __syncthreads();
        aP += 8; bP += 8;
        float4 av, bv;
        bool more = (k0 + 8 < K);
        if (more) { av = *(const float4*)aP; bv = *(const float4*)bP; }
#pragma unroll
        for (int k = 0; k < 8; k++) {
            float4 a0 = *(const float4*)&As[cur][k][ty * 8];
            float4 a1 = *(const float4*)&As[cur][k][ty * 8 + 4];
            ull b0 = *(const ull*)&Bs[cur][k][tx * 8];
            ull b1 = *(const ull*)&Bs[cur][k][tx * 8 + 2];
            ull b2 = *(const ull*)&Bs[cur][k][tx * 8 + 4];
            ull b3 = *(const ull*)&Bs[cur][k][tx * 8 + 6];
            float a[8] = {a0.x, a0.y, a0.z, a0.w, a1.x, a1.y, a1.z, a1.w};
#pragma unroll
            for (int i = 0; i < 8; i++) {
                ull a2 = pk2(a[i], a[i]);
                f2fma(acc[i][0], a2, b0);
                f2fma(acc[i][1], a2, b1);
                f2fma(acc[i][2], a2, b2);
                f2fma(acc[i][3], a2, b3);
            }
        }
        if (more) {
            int nxt = cur ^ 1;
            As[nxt][lk + 0][lr] = av.x; As[nxt][lk + 1][lr] = av.y;
            As[nxt][lk + 2][lr] = av.z; As[nxt][lk + 3][lr] = av.w;
            Bs[nxt][lk + 0][lr] = bv.x; Bs[nxt][lk + 1][lr] = bv.y;
            Bs[nxt][lk + 2][lr] = bv.z; Bs[nxt][lk + 3][lr] = bv.w;
        }
        cur ^= 1;
    }

    float bb[8];
#pragma unroll
    for (int jj = 0; jj < 8; jj++) bb[jj] = bias ? bias[n0 + tx * 8 + jj] : 0.f;
#pragma unroll
    for (int i = 0; i < 8; i++) {
        float2 p0 = upk2(acc[i][0]), p1 = upk2(acc[i][1]);
        float2 p2 = upk2(acc[i][2]), p3 = upk2(acc[i][3]);
        float4 v0 = make_float4(p0.x + bb[0], p0.y + bb[1], p1.x + bb[2], p1.y + bb[3]);
        float4 v1 = make_float4(p2.x + bb[4], p2.y + bb[5], p3.x + bb[6], p3.y + bb[7]);
        float* cp = C + (long long)(m0 + ty * 8 + i) * ldc + n0 + tx * 8;
        *(float4*)cp = v0;
        *(float4*)(cp + 4) = v1;
    }
}

// ===========================================================================
// C[M,N] = A[M,K] * B[K,N]  (A K-contig rows, B N-contig rows).
// v3: same double-buffered single-sync pipeline.
// ===========================================================================
__global__ void __launch_bounds__(256, 2) gemm_nn_kernel(
    const float* __restrict__ A, const float* __restrict__ B,
    float* __restrict__ C,
    int K, long long lda, long long ldb, long long ldc,
    long long bsA, long long bsB, long long bsC)
{
    __shared__ __align__(16) float As[2][8][128];
    __shared__ __align__(16) float Bs[2][8][128];
    long long bz = blockIdx.z;
    A += bz * bsA; B += bz * bsB; C += bz * bsC;
    int m0 = blockIdx.x * 128, n0 = blockIdx.y * 128;
    int tid = threadIdx.x;
    int lr = tid >> 1, lk = (tid & 1) * 4;
    const float* aP = A + (long long)(m0 + lr) * lda + lk;
    int bRow = tid >> 5, bCol = (tid & 31) * 4;
    const float* bP = B + (long long)bRow * ldb + n0 + bCol;
    int ty = tid >> 4, tx = tid & 15;

    ull acc[8][4];
#pragma unroll
    for (int i = 0; i < 8; i++)
#pragma unroll
        for (int j = 0; j < 4; j++) acc[i][j] = 0ull;

    {
        float4 av = *(const float4*)aP;
        float4 bv = *(const float4*)bP;
        As[0][lk + 0][lr] = av.x; As[0][lk + 1][lr] = av.y;
        As[0][lk + 2][lr] = av.z; As[0][lk + 3][lr] = av.w;
        *(float4*)&Bs[0][bRow][bCol] = bv;
    }

    int cur = 0;
    for (int k0 = 0; k0 < K; k0 += 8) {
        __syncthreads();
        aP += 8; bP += 8 * ldb;
        float4 av, bv;
        bool more = (k0 + 8 < K);
        if (more) { av = *(const float4*)aP; bv = *(const float4*)bP; }
#pragma unroll
        for (int k = 0; k < 8; k++) {
            float4 a0 = *(const float4*)&As[cur][k][ty * 8];
            float4 a1 = *(const float4*)&As[cur][k][ty * 8 + 4];
            ull b0 = *(const ull*)&Bs[cur][k][tx * 8];
            ull b1 = *(const ull*)&Bs[cur][k][tx * 8 + 2];
            ull b2 = *(const ull*)&Bs[cur][k][tx * 8 + 4];
            ull b3 = *(const ull*)&Bs[cur][k][tx * 8 + 6];
            float a[8] = {a0.x, a0.y, a0.z, a0.w, a1.x, a1.y, a1.z, a1.w};
#pragma unroll
            for (int i = 0; i < 8; i++) {
                ull a2 = pk2(a[i], a[i]);
                f2fma(acc[i][0], a2, b0);
                f2fma(acc[i][1], a2, b1);
                f2fma(acc[i][2], a2, b2);
                f2fma(acc[i][3], a2, b3);
            }
        }
        if (more) {
            int nxt = cur ^ 1;
            As[nxt][lk + 0][lr] = av.x; As[nxt][lk + 1][lr] = av.y;
            As[nxt][lk + 2][lr] = av.z; As[nxt][lk + 3][lr] = av.w;
            *(float4*)&Bs[nxt][bRow][bCol] = bv;
        }
        cur ^= 1;
    }

#pragma unroll
    for (int i = 0; i < 8; i++) {
        float2 p0 = upk2(acc[i][0]), p1 = upk2(acc[i][1]);
        float2 p2 = upk2(acc[i][2]), p3 = upk2(acc[i][3]);
        float* cp = C + (long long)(m0 + ty * 8 + i) * ldc + n0 + tx * 8;
        *(float4*)cp = make_float4(p0.x, p0.y, p1.x, p1.y);
        *(float4*)(cp + 4) = make_float4(p2.x, p2.y, p3.x, p3.y);
    }
}

// ===========================================================================
// Masked softmax over l (PLEN) per (s, b). Writes attnT[b][s][l] and attn out.
// ===========================================================================
__global__ void __launch_bounds__(256) softmax_kernel(
    const float* __restrict__ scores, const int* __restrict__ post_length,
    float* __restrict__ attnT, float* __restrict__ attn_out)
{
    __shared__ float sm[256];
    int s = blockIdx.x, b = blockIdx.y, l = threadIdx.x;
    float sc = scores[((long long)b * S_LEN + s) * PLEN + l];
    if (l >= post_length[b]) sc = NEGV;
    sm[l] = sc; __syncthreads();
    for (int o = 128; o > 0; o >>= 1) {
        if (l < o) sm[l] = fmaxf(sm[l], sm[l + o]);
        __syncthreads();
    }
    float mx = sm[0]; __syncthreads();
    float e = expf(sc - mx);
    sm[l] = e; __syncthreads();
    for (int o = 128; o > 0; o >>= 1) {
        if (l < o) sm[l] += sm[l + o];
        __syncthreads();
    }
    float a = e / sm[0];
    attnT[((long long)b * S_LEN + s) * PLEN + l] = a;
    attn_out[(long long)s * (PLEN * BATCH) + (long long)l * BATCH + b] = a;
}

// h_last = hs[255][:, :1024]
__global__ void hlast_kernel(const float* __restrict__ src, float* __restrict__ dst)
{
    int b = blockIdx.x, t = threadIdx.x;
    float4 v = *(const float4*)(src + (long long)b * 2048 + t * 4);
    *(float4*)(dst + (long long)b * 1024 + t * 4) = v;
}

// ===========================================================================
extern "C" void kernel_launch(void* const* d_in, const int* in_sizes, int n_in,
                              void* d_out, int out_size)
{
    const float* incoming = (const float*)d_in[0];   // [256,64,1024]
    const float* post     = (const float*)d_in[1];   // [256,64,1024]
    const float* h_init   = (const float*)d_in[2];   // [1,1,1024]
    const float* W_ih     = (const float*)d_in[3];   // [3072,1024]
    const float* W_hh     = (const float*)d_in[4];   // [3072,1024]
    const float* b_ih     = (const float*)d_in[5];   // [3072]
    const float* b_hh     = (const float*)d_in[6];   // [3072]
    const float* Wq       = (const float*)d_in[7];   // [1024,1024]
    const float* bq       = (const float*)d_in[8];   // [1024]
    const int*   length   = (const int*)d_in[9];     // [64]
    const int*   plen     = (const int*)d_in[10];    // [64]
    float* out = (float*)d_out;

    float *gi, *q, *scores, *attnT;
    cudaGetSymbolAddress((void**)&gi,     g_gi);
    cudaGetSymbolAddress((void**)&q,      g_q);
    cudaGetSymbolAddress((void**)&scores, g_scores);
    cudaGetSymbolAddress((void**)&attnT,  g_attnT);

    cudaFuncSetAttribute(recurrence3_kernel,
                         cudaFuncAttributeMaxDynamicSharedMemorySize, SM_TOTAL);

    // 1) gi = incoming @ W_ih^T + b_ih : [16384, 3072], K=1024
    gemm_nt_kernel<<<dim3(128, 24, 1), 256>>>(
        incoming, W_ih, b_ih, gi, 1024, 1024, 1024, 3072, 0, 0, 0);

    // 2) recurrence: one persistent kernel (barrier reset + transposed h init)
    init_kernel<<<64, 512>>>(h_init);
    recurrence3_kernel<<<GRID_P, 256, SM_TOTAL>>>(
        W_hh, gi, b_hh, length, out + HS_OFF);

    // 3) queries = hs_h @ Wq^T + bq : [16384, 1024], A stride 2048
    gemm_nt_kernel<<<dim3(128, 8, 1), 256>>>(
        out + HS_OFF, Wq, bq, q, 1024, 2048, 1024, 1024, 0, 0, 0);

    // 4) scores[b][s][l] = q[s,b,:] . post[l,b,:]  (batched over b)
    gemm_nt_kernel<<<dim3(2, 2, 64), 256>>>(
        q, post, (const float*)0, scores, 1024,
        (long long)BATCH * PSZ, (long long)BATCH * PSZ, PLEN,
        PSZ, PSZ, (long long)S_LEN * PLEN);

    // 5) masked softmax over l; writes attnT and the attn output block
    softmax_kernel<<<dim3(256, 64), 256>>>(scores, plen, attnT, out + ATTN_OFF);

    // 6) context[s][b][p] = attnT[b][s][:] @ post[:,b,:]  (batched over b)
    gemm_nn_kernel<<<dim3(2, 8, 64), 256>>>(
        attnT, post, out + HS_OFF + 1024, PLEN,
        PLEN, (long long)BATCH * PSZ, (long long)BATCH * 2048,
        (long long)S_LEN * PLEN, PSZ, 2048);

    // 7) h_last = hs[255, :, :1024]
    hlast_kernel<<<64, 256>>>(out + HS_OFF + (long long)255 * BATCH * 2048, out);
}

// round 17
// speedup vs baseline: 1.7639x; 1.0329x over previous
#include <cuda_runtime.h>
#include <math.h>
#include <stdint.h>

// Problem shapes (fixed)
#define S_LEN 256
#define BATCH 64
#define HSZ   1024
#define H3    3072
#define PLEN  256
#define PSZ   1024
// Output layout: [h_last (64*1024) | hs (256*64*2048) | attn (256*256*64)]
#define HS_OFF   65536
#define ATTN_OFF 33619968
#define NEGV -1000000000.0f

// Persistent recurrence config
#define GRID_P 128          // 128 CTAs, each owns 8 hidden units (all 3 gates)
// dynamic smem layout (bytes)
#define SM_W    0           // Wsm[24][1024] floats            = 98304
#define SM_HS   98304       // Hs[2][4 kss][16 k2][64 b] ull   = 65536
#define SM_RED  163840      // red[4][24][66] floats           = 25344
#define SM_TOTAL 189184
#define HSBUF   32768       // one Hs buffer (4*16*64*8)

typedef unsigned long long ull;

// ---------------- device scratch (no runtime allocation allowed) -----------
__device__ float g_gi[(size_t)S_LEN * BATCH * H3];       // 201 MB
__device__ float g_q[(size_t)S_LEN * BATCH * PSZ];       //  64 MB
__device__ float g_scores[(size_t)BATCH * S_LEN * PLEN]; //  16 MB
__device__ float g_attnT[(size_t)BATCH * S_LEN * PLEN];  //  16 MB
__device__ ull   g_hbufT[2][512][64];                    // 512 KB, [p][k/2][b] packed pairs
__device__ ull   g_bar;

// ---------------- packed fp32x2 helpers (Blackwell FFMA2 path) -------------
__device__ __forceinline__ ull pk2(float lo, float hi) {
    ull r;
    asm("mov.b64 %0, {%1, %2};" : "=l"(r) : "f"(lo), "f"(hi));
    return r;
}
__device__ __forceinline__ float2 upk2(ull v) {
    float2 r;
    asm("mov.b64 {%0, %1}, %2;" : "=f"(r.x), "=f"(r.y) : "l"(v));
    return r;
}
__device__ __forceinline__ void f2fma(ull &c, ull a, ull b) {
    asm("fma.rn.f32x2 %0, %1, %2, %0;" : "+l"(c) : "l"(a), "l"(b));
}

// ---------------- cp.async helpers ----------------------------------------
__device__ __forceinline__ void cp16(uint32_t dst, const void* src) {
    asm volatile("cp.async.cg.shared.global [%0], [%1], 16;\n"
                 :: "r"(dst), "l"(src) : "memory");
}
#define CP_COMMIT() asm volatile("cp.async.commit_group;\n" ::: "memory")
#define CP_WAIT1()  asm volatile("cp.async.wait_group 1;\n" ::: "memory")

// ---------------- grid-wide barrier ----------------------------------------
__device__ __forceinline__ void grid_bar() {
    __threadfence();          // release my writes
    __syncthreads();
    if (threadIdx.x == 0) {
        ull t = atomicAdd(&g_bar, 1ULL) + 1ULL;
        ull target = ((t + GRID_P - 1) / GRID_P) * GRID_P;
        while (*((volatile ull*)&g_bar) < target) { }
        __threadfence();      // acquire
    }
    __syncthreads();
}

// ===========================================================================
// init: reset barrier counter, broadcast h_init into transposed ping buffer 0
// grid 64 (batch), 512 threads (k2)
// ===========================================================================
__global__ void init_kernel(const float* __restrict__ h_init) {
    if (blockIdx.x == 0 && threadIdx.x == 0) g_bar = 0ULL;
    int b = blockIdx.x, k2 = threadIdx.x;
    g_hbufT[0][k2][b] = pk2(h_init[2 * k2], h_init[2 * k2 + 1]);
}

// ===========================================================================
// Persistent recurrence kernel v3 (unchanged from R15).
// ===========================================================================
__global__ void __launch_bounds__(256) recurrence3_kernel(
    const float* __restrict__ W, const float* __restrict__ gi,
    const float* __restrict__ bhh, const int* __restrict__ length,
    float* __restrict__ hs_out)
{
    extern __shared__ __align__(16) char smem[];
    float* Wsm = (float*)(smem + SM_W);     // [24][1024]
    float* red = (float*)(smem + SM_RED);   // [4][24][66]
    uint32_t sb;
    asm("{ .reg .u64 t; cvta.to.shared.u64 t, %1; cvt.u32.u64 %0, t; }"
        : "=r"(sb) : "l"(smem));
    const uint32_t hs_u32 = sb + SM_HS;

    const int c = blockIdx.x, tid = threadIdx.x;
    const int w = tid >> 5, lane = tid & 31;
    const int ks = w >> 1, rg = w & 1;      // k-slice 0..3 (256k), row-half 0..1

    // ---- load W rows (gathered {r,z,n} x 8 units) once, coalesced ----
    for (int idx = tid; idx < 24 * 256; idx += 256) {
        int u = idx >> 8, f4 = idx & 255;
        long long grow = (long long)(u >> 3) * 1024 + c * 8 + (u & 7);
        *(float4*)&Wsm[u * 1024 + f4 * 4] =
            *(const float4*)&W[grow * 1024 + f4 * 4];
    }

    // ---- phase-B mapping: 2 adjacent units x 1 batch per thread ----
    const int j2 = tid >> 6;        // 0..3 (unit pair)
    const int gb = tid & 63;        // batch
    const float2 brv = *(const float2*)&bhh[c * 8 + j2 * 2];
    const float2 bzv = *(const float2*)&bhh[HSZ + c * 8 + j2 * 2];
    const float2 bnv = *(const float2*)&bhh[2 * HSZ + c * 8 + j2 * 2];
    const int mylen = length[gb];

    __syncthreads();

    int p = 0;
    for (int s = 0; s < S_LEN; s++) {
        const ull* hsrc = &g_hbufT[p][0][0];

        // ---- prefetch phase-B operands (independent of phase A) ----
        const float* gib = gi + ((long long)s * BATCH + gb) * H3 + c * 8 + j2 * 2;
        float2 gir = *(const float2*)gib;
        float2 giz = *(const float2*)(gib + HSZ);
        float2 gin = *(const float2*)(gib + 2 * HSZ);
        ull hpq = g_hbufT[p][c * 4 + j2][gb];

        // ---- prologue: stage chunks 0,1 (32 KB each, contiguous copy) ----
#pragma unroll
        for (int cj = 0; cj < 2; cj++) {
#pragma unroll
            for (int i = 0; i < 8; i++) {
                int idx = tid + i * 256;                    // 0..2047
                int kss = idx >> 9, k2l = (idx >> 5) & 15, bp = idx & 31;
                cp16(hs_u32 + cj * HSBUF + kss * 8192 + k2l * 512 + bp * 16,
                     hsrc + (kss * 128 + cj * 16 + k2l) * 64 + bp * 2);
            }
            CP_COMMIT();
        }

        ull acc[12][2];
#pragma unroll
        for (int r = 0; r < 12; r++) { acc[r][0] = 0ull; acc[r][1] = 0ull; }

        for (int cj = 0; cj < 8; cj++) {
            CP_WAIT1();
            __syncthreads();
            const char* hb = smem + SM_HS + (cj & 1) * HSBUF + ks * 8192;
#pragma unroll
            for (int kp = 0; kp < 8; kp++) {                // 2 k2 (4 k) per kp
                ull hA0 = *(const ull*)(hb + (kp * 2 + 0) * 512 + lane * 8);
                ull hA1 = *(const ull*)(hb + (kp * 2 + 1) * 512 + lane * 8);
                ull hB0 = *(const ull*)(hb + (kp * 2 + 0) * 512 + 256 + lane * 8);
                ull hB1 = *(const ull*)(hb + (kp * 2 + 1) * 512 + 256 + lane * 8);
#pragma unroll
                for (int r = 0; r < 12; r++) {
                    ulonglong2 wv = *(const ulonglong2*)
                        &Wsm[(rg * 12 + r) * 1024 + ks * 256 + cj * 32 + kp * 4];
                    f2fma(acc[r][0], wv.x, hA0);
                    f2fma(acc[r][0], wv.y, hA1);
                    f2fma(acc[r][1], wv.x, hB0);
                    f2fma(acc[r][1], wv.y, hB1);
                }
            }
            __syncthreads();        // all warps done reading buffer (cj&1)
            if (cj + 2 < 8) {
#pragma unroll
                for (int i = 0; i < 8; i++) {
                    int idx = tid + i * 256;
                    int kss = idx >> 9, k2l = (idx >> 5) & 15, bp = idx & 31;
                    cp16(hs_u32 + (cj & 1) * HSBUF + kss * 8192 + k2l * 512 + bp * 16,
                         hsrc + (kss * 128 + (cj + 2) * 16 + k2l) * 64 + bp * 2);
                }
            }
            CP_COMMIT();
        }

        // ---- reduce: per-slice partials (pair-summed over even/odd k) ----
#pragma unroll
        for (int r = 0; r < 12; r++) {
            int u = rg * 12 + r;
            float2 e0 = upk2(acc[r][0]);
            float2 e1 = upk2(acc[r][1]);
            red[(ks * 24 + u) * 66 + lane]      = e0.x + e0.y;
            red[(ks * 24 + u) * 66 + lane + 32] = e1.x + e1.y;
        }
        __syncthreads();

        // ---- phase B: gates for units (j2*2, j2*2+1) of batch gb ----
        {
            float sr0 = 0, sr1 = 0, sz0 = 0, sz1 = 0, sn0 = 0, sn1 = 0;
#pragma unroll
            for (int k4 = 0; k4 < 4; k4++) {
                int base = k4 * 24;
                sr0 += red[(base + j2 * 2 + 0) * 66 + gb];
                sr1 += red[(base + j2 * 2 + 1) * 66 + gb];
                sz0 += red[(base + 8 + j2 * 2 + 0) * 66 + gb];
                sz1 += red[(base + 8 + j2 * 2 + 1) * 66 + gb];
                sn0 += red[(base + 16 + j2 * 2 + 0) * 66 + gb];
                sn1 += red[(base + 16 + j2 * 2 + 1) * 66 + gb];
            }
            float2 hp = upk2(hpq);
            float keep = (s < mylen) ? 1.f : 0.f;

            float r0 = 1.f / (1.f + expf(-(gir.x + sr0 + brv.x)));
            float r1 = 1.f / (1.f + expf(-(gir.y + sr1 + brv.y)));
            float z0 = 1.f / (1.f + expf(-(giz.x + sz0 + bzv.x)));
            float z1 = 1.f / (1.f + expf(-(giz.y + sz1 + bzv.y)));
            float n0 = tanhf(gin.x + r0 * (sn0 + bnv.x));
            float n1 = tanhf(gin.y + r1 * (sn1 + bnv.y));
            float h0 = (n0 + z0 * (hp.x - n0)) * keep;
            float h1 = (n1 + z1 * (hp.y - n1)) * keep;

            g_hbufT[p ^ 1][c * 4 + j2][gb] = pk2(h0, h1);
            *(float2*)&hs_out[((long long)s * BATCH + gb) * 2048 + c * 8 + j2 * 2] =
                make_float2(h0, h1);
        }
        grid_bar();
        p ^= 1;
    }
}

// ===========================================================================
// C[M,N] = A[M,K] * B[N,K]^T (+bias). A,B K-contiguous.
// v4: 256x128 CTA tile, BK=8, 256 threads, 16x8 per-thread microtile.
// Wavefront math: 4 LDS.128 (A) + 2 LDS.128 (B) per warp-k = 24 wf vs 256
// FFMA2-cycles/SMSP -> fma-bound (was wavefront-bound at 8x8).
// Requires M%256==0, N%128==0, K%8==0.
// ===========================================================================
__global__ void __launch_bounds__(256) gemm_nt_kernel(
    const float* __restrict__ A, const float* __restrict__ B,
    const float* __restrict__ bias, float* __restrict__ C,
    int K, long long lda, long long ldb, long long ldc,
    long long bsA, long long bsB, long long bsC)
{
    __shared__ __align__(16) float As[2][8][256];
    __shared__ __align__(16) float Bs[2][8][128];
    long long bz = blockIdx.z;
    A += bz * bsA; B += bz * bsB; C += bz * bsC;
    int m0 = blockIdx.x * 256, n0 = blockIdx.y * 128;
    int tid = threadIdx.x;
    int lr = tid >> 1, lk = (tid & 1) * 4;   // loader: 2 threads per row
    const float* aP0 = A + (long long)(m0 + lr) * lda + lk;
    const float* aP1 = A + (long long)(m0 + 128 + lr) * lda + lk;
    const float* bP  = B + (long long)(n0 + lr) * ldb + lk;
    int ty = tid >> 4, tx = tid & 15;        // compute: rows ty*16..+15, cols tx*8..+7

    ull acc[16][4];
#pragma unroll
    for (int i = 0; i < 16; i++)
#pragma unroll
        for (int j = 0; j < 4; j++) acc[i][j] = 0ull;

    // tile 0 -> buf 0
    {
        float4 a0 = *(const float4*)aP0;
        float4 a1 = *(const float4*)aP1;
        float4 bv = *(const float4*)bP;
        As[0][lk + 0][lr] = a0.x; As[0][lk + 1][lr] = a0.y;
        As[0][lk + 2][lr] = a0.z; As[0][lk + 3][lr] = a0.w;
        As[0][lk + 0][128 + lr] = a1.x; As[0][lk + 1][128 + lr] = a1.y;
        As[0][lk + 2][128 + lr] = a1.z; As[0][lk + 3][128 + lr] = a1.w;
        Bs[0][lk + 0][lr] = bv.x; Bs[0][lk + 1][lr] = bv.y;
        Bs[0][lk + 2][lr] = bv.z; Bs[0][lk + 3][lr] = bv.w;
    }

    int cur = 0;
    for (int k0 = 0; k0 < K; k0 += 8) {
        __syncthreads();
        aP0 += 8; aP1 += 8; bP += 8;
        float4 pa0, pa1, pbv;
        bool more = (k0 + 8 < K);
        if (more) {
            pa0 = *(const float4*)aP0;
            pa1 = *(const float4*)aP1;
            pbv = *(const float4*)bP;
        }
#pragma unroll
        for (int k = 0; k < 8; k++) {
            float4 a0 = *(const float4*)&As[cur][k][ty * 16];
            float4 a1 = *(const float4*)&As[cur][k][ty * 16 + 4];
            float4 a2 = *(const float4*)&As[cur][k][ty * 16 + 8];
            float4 a3 = *(const float4*)&As[cur][k][ty * 16 + 12];
            ulonglong2 bv0 = *(const ulonglong2*)&Bs[cur][k][tx * 8];
            ulonglong2 bv1 = *(const ulonglong2*)&Bs[cur][k][tx * 8 + 4];
            float a[16] = {a0.x, a0.y, a0.z, a0.w, a1.x, a1.y, a1.z, a1.w,
                           a2.x, a2.y, a2.z, a2.w, a3.x, a3.y, a3.z, a3.w};
#pragma unroll
            for (int i = 0; i < 16; i++) {
                ull s2 = pk2(a[i], a[i]);
                f2fma(acc[i][0], s2, bv0.x);
                f2fma(acc[i][1], s2, bv0.y);
                f2fma(acc[i][2], s2, bv1.x);
                f2fma(acc[i][3], s2, bv1.y);
            }
        }
        if (more) {
            int nxt = cur ^ 1;
            As[nxt][lk + 0][lr] = pa0.x; As[nxt][lk + 1][lr] = pa0.y;
            As[nxt][lk + 2][lr] = pa0.z; As[nxt][lk + 3][lr] = pa0.w;
            As[nxt][lk + 0][128 + lr] = pa1.x; As[nxt][lk + 1][128 + lr] = pa1.y;
            As[nxt][lk + 2][128 + lr] = pa1.z; As[nxt][lk + 3][128 + lr] = pa1.w;
            Bs[nxt][lk + 0][lr] = pbv.x; Bs[nxt][lk + 1][lr] = pbv.y;
            Bs[nxt][lk + 2][lr] = pbv.z; Bs[nxt][lk + 3][lr] = pbv.w;
        }
        cur ^= 1;
    }

    float bb[8];
#pragma unroll
    for (int jj = 0; jj < 8; jj++) bb[jj] = bias ? bias[n0 + tx * 8 + jj] : 0.f;
#pragma unroll
    for (int i = 0; i < 16; i++) {
        float2 p0 = upk2(acc[i][0]), p1 = upk2(acc[i][1]);
        float2 p2 = upk2(acc[i][2]), p3 = upk2(acc[i][3]);
        float4 v0 = make_float4(p0.x + bb[0], p0.y + bb[1], p1.x + bb[2], p1.y + bb[3]);
        float4 v1 = make_float4(p2.x + bb[4], p2.y + bb[5], p3.x + bb[6], p3.y + bb[7]);
        float* cp = C + (long long)(m0 + ty * 16 + i) * ldc + n0 + tx * 8;
        *(float4*)cp = v0;
        *(float4*)(cp + 4) = v1;
    }
}

// ===========================================================================
// C[M,N] = A[M,K] * B[K,N]  (A K-contig rows, B N-contig rows).
// v3 double-buffered (unchanged). Used for context = attnT @ post.
// ===========================================================================
__global__ void __launch_bounds__(256, 2) gemm_nn_kernel(
    const float* __restrict__ A, const float* __restrict__ B,
    float* __restrict__ C,
    int K, long long lda, long long ldb, long long ldc,
    long long bsA, long long bsB, long long bsC)
{
    __shared__ __align__(16) float As[2][8][128];
    __shared__ __align__(16) float Bs[2][8][128];
    long long bz = blockIdx.z;
    A += bz * bsA; B += bz * bsB; C += bz * bsC;
    int m0 = blockIdx.x * 128, n0 = blockIdx.y * 128;
    int tid = threadIdx.x;
    int lr = tid >> 1, lk = (tid & 1) * 4;
    const float* aP = A + (long long)(m0 + lr) * lda + lk;
    int bRow = tid >> 5, bCol = (tid & 31) * 4;
    const float* bP = B + (long long)bRow * ldb + n0 + bCol;
    int ty = tid >> 4, tx = tid & 15;

    ull acc[8][4];
#pragma unroll
    for (int i = 0; i < 8; i++)
#pragma unroll
        for (int j = 0; j < 4; j++) acc[i][j] = 0ull;

    {
        float4 av = *(const float4*)aP;
        float4 bv = *(const float4*)bP;
        As[0][lk + 0][lr] = av.x; As[0][lk + 1][lr] = av.y;
        As[0][lk + 2][lr] = av.z; As[0][lk + 3][lr] = av.w;
        *(float4*)&Bs[0][bRow][bCol] = bv;
    }

    int cur = 0;
    for (int k0 = 0; k0 < K; k0 += 8) {
        __syncthreads();
        aP += 8; bP += 8 * ldb;
        float4 av, bv;
        bool more = (k0 + 8 < K);
        if (more) { av = *(const float4*)aP; bv = *(const float4*)bP; }
#pragma unroll
        for (int k = 0; k < 8; k++) {
            float4 a0 = *(const float4*)&As[cur][k][ty * 8];
            float4 a1 = *(const float4*)&As[cur][k][ty * 8 + 4];
            ull b0 = *(const ull*)&Bs[cur][k][tx * 8];
            ull b1 = *(const ull*)&Bs[cur][k][tx * 8 + 2];
            ull b2 = *(const ull*)&Bs[cur][k][tx * 8 + 4];
            ull b3 = *(const ull*)&Bs[cur][k][tx * 8 + 6];
            float a[8] = {a0.x, a0.y, a0.z, a0.w, a1.x, a1.y, a1.z, a1.w};
#pragma unroll
            for (int i = 0; i < 8; i++) {
                ull a2 = pk2(a[i], a[i]);
                f2fma(acc[i][0], a2, b0);
                f2fma(acc[i][1], a2, b1);
                f2fma(acc[i][2], a2, b2);
                f2fma(acc[i][3], a2, b3);
            }
        }
        if (more) {
            int nxt = cur ^ 1;
            As[nxt][lk + 0][lr] = av.x; As[nxt][lk + 1][lr] = av.y;
            As[nxt][lk + 2][lr] = av.z; As[nxt][lk + 3][lr] = av.w;
            *(float4*)&Bs[nxt][bRow][bCol] = bv;
        }
        cur ^= 1;
    }

#pragma unroll
    for (int i = 0; i < 8; i++) {
        float2 p0 = upk2(acc[i][0]), p1 = upk2(acc[i][1]);
        float2 p2 = upk2(acc[i][2]), p3 = upk2(acc[i][3]);
        float* cp = C + (long long)(m0 + ty * 8 + i) * ldc + n0 + tx * 8;
        *(float4*)cp = make_float4(p0.x, p0.y, p1.x, p1.y);
        *(float4*)(cp + 4) = make_float4(p2.x, p2.y, p3.x, p3.y);
    }
}

// ===========================================================================
// Masked softmax over l (PLEN) per (s, b). Writes attnT[b][s][l] and attn out.
// ===========================================================================
__global__ void __launch_bounds__(256) softmax_kernel(
    const float* __restrict__ scores, const int* __restrict__ post_length,
    float* __restrict__ attnT, float* __restrict__ attn_out)
{
    __shared__ float sm[256];
    int s = blockIdx.x, b = blockIdx.y, l = threadIdx.x;
    float sc = scores[((long long)b * S_LEN + s) * PLEN + l];
    if (l >= post_length[b]) sc = NEGV;
    sm[l] = sc; __syncthreads();
    for (int o = 128; o > 0; o >>= 1) {
        if (l < o) sm[l] = fmaxf(sm[l], sm[l + o]);
        __syncthreads();
    }
    float mx = sm[0]; __syncthreads();
    float e = expf(sc - mx);
    sm[l] = e; __syncthreads();
    for (int o = 128; o > 0; o >>= 1) {
        if (l < o) sm[l] += sm[l + o];
        __syncthreads();
    }
    float a = e / sm[0];
    attnT[((long long)b * S_LEN + s) * PLEN + l] = a;
    attn_out[(long long)s * (PLEN * BATCH) + (long long)l * BATCH + b] = a;
}

// h_last = hs[255][:, :1024]
__global__ void hlast_kernel(const float* __restrict__ src, float* __restrict__ dst)
{
    int b = blockIdx.x, t = threadIdx.x;
    float4 v = *(const float4*)(src + (long long)b * 2048 + t * 4);
    *(float4*)(dst + (long long)b * 1024 + t * 4) = v;
}

// ===========================================================================
extern "C" void kernel_launch(void* const* d_in, const int* in_sizes, int n_in,
                              void* d_out, int out_size)
{
    const float* incoming = (const float*)d_in[0];   // [256,64,1024]
    const float* post     = (const float*)d_in[1];   // [256,64,1024]
    const float* h_init   = (const float*)d_in[2];   // [1,1,1024]
    const float* W_ih     = (const float*)d_in[3];   // [3072,1024]
    const float* W_hh     = (const float*)d_in[4];   // [3072,1024]
    const float* b_ih     = (const float*)d_in[5];   // [3072]
    const float* b_hh     = (const float*)d_in[6];   // [3072]
    const float* Wq       = (const float*)d_in[7];   // [1024,1024]
    const float* bq       = (const float*)d_in[8];   // [1024]
    const int*   length   = (const int*)d_in[9];     // [64]
    const int*   plen     = (const int*)d_in[10];    // [64]
    float* out = (float*)d_out;

    float *gi, *q, *scores, *attnT;
    cudaGetSymbolAddress((void**)&gi,     g_gi);
    cudaGetSymbolAddress((void**)&q,      g_q);
    cudaGetSymbolAddress((void**)&scores, g_scores);
    cudaGetSymbolAddress((void**)&attnT,  g_attnT);

    cudaFuncSetAttribute(recurrence3_kernel,
                         cudaFuncAttributeMaxDynamicSharedMemorySize, SM_TOTAL);

    // 1) gi = incoming @ W_ih^T + b_ih : [16384, 3072], K=1024
    gemm_nt_kernel<<<dim3(64, 24, 1), 256>>>(
        incoming, W_ih, b_ih, gi, 1024, 1024, 1024, 3072, 0, 0, 0);

    // 2) recurrence: one persistent kernel (barrier reset + transposed h init)
    init_kernel<<<64, 512>>>(h_init);
    recurrence3_kernel<<<GRID_P, 256, SM_TOTAL>>>(
        W_hh, gi, b_hh, length, out + HS_OFF);

    // 3) queries = hs_h @ Wq^T + bq : [16384, 1024], A stride 2048
    gemm_nt_kernel<<<dim3(64, 8, 1), 256>>>(
        out + HS_OFF, Wq, bq, q, 1024, 2048, 1024, 1024, 0, 0, 0);

    // 4) scores[b][s][l] = q[s,b,:] . post[l,b,:]  (batched over b)
    gemm_nt_kernel<<<dim3(1, 2, 64), 256>>>(
        q, post, (const float*)0, scores, 1024,
        (long long)BATCH * PSZ, (long long)BATCH * PSZ, PLEN,
        PSZ, PSZ, (long long)S_LEN * PLEN);

    // 5) masked softmax over l; writes attnT and the attn output block
    softmax_kernel<<<dim3(256, 64), 256>>>(scores, plen, attnT, out + ATTN_OFF);

    // 6) context[s][b][p] = attnT[b][s][:] @ post[:,b,:]  (batched over b)
    gemm_nn_kernel<<<dim3(2, 8, 64), 256>>>(
        attnT, post, out + HS_OFF + 1024, PLEN,
        PLEN, (long long)BATCH * PSZ, (long long)BATCH * 2048,
        (long long)S_LEN * PLEN, PSZ, 2048);

    // 7) h_last = hs[255, :, :1024]
    hlast_kernel<<<64, 256>>>(out + HS_OFF + (long long)255 * BATCH * 2048, out);
}